// round 3
// baseline (speedup 1.0000x reference)
#include <cuda_runtime.h>
#include <cstdint>

#define B_ROOT   8192
#define KFAN     16
#define NCHILD   (B_ROOT * KFAN)     // 131072
#define VOCAB    50000
#define DIM      64
#define CR       8
#define NR       64
#define CC       16
#define NC       128
#define OUTD     32
#define KDIM     (CC * DIM + NC)     // 1152
#define OUTCOLS  (CR * DIM + NR + OUTD)  // 608
#define EPSBN    1e-5f
#define WPAD     36                  // smem row pad (multiple of 4 -> 16B aligned LDS.128)

// ---------------- scratch (device globals; allocation-free) ----------------
__device__ __align__(16) double g_sum_c[NC];
__device__ __align__(16) double g_ss_c [NC];
__device__ __align__(16) double g_sum_r[NR];
__device__ __align__(16) double g_ss_r [NR];
__device__ __align__(16) float g_a_c[NC];   // gamma * rsqrt(var+eps)
__device__ __align__(16) float g_s_c[NC];   // beta - mean * a
__device__ __align__(16) float g_a_r[NR];
__device__ __align__(16) float g_s_r[NR];

// ---------------- packed f32x2 helpers ----------------
__device__ __forceinline__ unsigned long long pack2(float a, float b) {
    unsigned long long r;
    asm("mov.b64 %0, {%1, %2};" : "=l"(r) : "f"(a), "f"(b));
    return r;
}
__device__ __forceinline__ void unpack2(unsigned long long v, float& lo, float& hi) {
    asm("mov.b64 {%0, %1}, %2;" : "=f"(lo), "=f"(hi) : "l"(v));
}
__device__ __forceinline__ void fma2(unsigned long long& d, unsigned long long a, unsigned long long b) {
    asm("fma.rn.f32x2 %0, %1, %2, %0;" : "+l"(d) : "l"(a), "l"(b));
}

// ---------------- kernel 0: reset stat accumulators ----------------
__global__ void k_reset() {
    int t = threadIdx.x;
    if (t < NC) { g_sum_c[t] = 0.0; g_ss_c[t] = 0.0; }
    if (t < NR) { g_sum_r[t] = 0.0; g_ss_r[t] = 0.0; }
}

// ---------------- kernel 1: child BN stats over gathered rows ----------------
__global__ void k_stats_child(const int* __restrict__ cfi, const float* __restrict__ child_num) {
    int col = threadIdx.x;
    int r0 = blockIdx.x * 256;
    double s = 0.0, ss = 0.0;
    for (int r = r0; r < r0 + 256; ++r) {
        int g = cfi[r];
        float x = child_num[(size_t)g * NC + col];
        s += (double)x; ss += (double)x * (double)x;
    }
    atomicAdd(&g_sum_c[col], s);
    atomicAdd(&g_ss_c[col], ss);
}

// ---------------- kernel 2: root BN stats ----------------
__global__ void k_stats_root(const int* __restrict__ idx, const float* __restrict__ root_num) {
    int col = threadIdx.x;
    int r0 = blockIdx.x * 256;
    double s = 0.0, ss = 0.0;
    for (int r = r0; r < r0 + 256; ++r) {
        int g = idx[r];
        float x = root_num[(size_t)g * NR + col];
        s += (double)x; ss += (double)x * (double)x;
    }
    atomicAdd(&g_sum_r[col], s);
    atomicAdd(&g_ss_r[col], ss);
}

// ---------------- kernel 3: finalize BN scale/shift ----------------
__global__ void k_finalize(const float* __restrict__ gamma_c, const float* __restrict__ beta_c,
                           const float* __restrict__ gamma_r, const float* __restrict__ beta_r) {
    int t = threadIdx.x;
    if (t < NC) {
        double m = g_sum_c[t] * (1.0 / (double)NCHILD);
        double v = g_ss_c[t] * (1.0 / (double)NCHILD) - m * m;
        float a = gamma_c[t] * rsqrtf((float)v + EPSBN);
        g_a_c[t] = a;
        g_s_c[t] = beta_c[t] - (float)m * a;
    }
    if (t < NR) {
        double m = g_sum_r[t] * (1.0 / (double)B_ROOT);
        double v = g_ss_r[t] * (1.0 / (double)B_ROOT) - m * m;
        float a = gamma_r[t] * rsqrtf((float)v + EPSBN);
        g_a_r[t] = a;
        g_s_r[t] = beta_r[t] - (float)m * a;
    }
}

// ---------------- kernel 4: root output (emb gather + BN nums) ----------------
__global__ void k_root(const int* __restrict__ idx, const int* __restrict__ root_cat,
                       const float* __restrict__ root_num, const float* __restrict__ emb_root,
                       float* __restrict__ out) {
    int warp = (blockIdx.x * blockDim.x + threadIdx.x) >> 5;
    int lane = threadIdx.x & 31;
    if (warp >= B_ROOT) return;
    int g = idx[warp];
    const int* cr = root_cat + (size_t)g * CR;
    float* orow = out + (size_t)warp * OUTCOLS;
#pragma unroll
    for (int c = 0; c < CR; ++c) {
        int v = cr[c];
        const float2* e = (const float2*)(emb_root + ((size_t)c * VOCAB + v) * DIM);
        *(float2*)(orow + c * DIM + lane * 2) = e[lane];
    }
    float2 x  = *(const float2*)(root_num + (size_t)g * NR + lane * 2);
    float2 a  = ((const float2*)g_a_r)[lane];
    float2 sh = ((const float2*)g_s_r)[lane];
    float2 y;
    y.x = fmaf(x.x, a.x, sh.x);
    y.y = fmaf(x.y, a.y, sh.y);
    *(float2*)(orow + CR * DIM + lane * 2) = y;
}

// ---------------- kernel 5: fused child (gather + BN + Linear + ReLU + mean) ----------------
__device__ __forceinline__ void fma_row(unsigned long long acc[16], const float* __restrict__ Wt,
                                        int k, float h) {
    unsigned long long hh = pack2(h, h);
    const ulonglong2* wrow = (const ulonglong2*)(Wt + k * WPAD);
#pragma unroll
    for (int p = 0; p < 8; ++p) {
        ulonglong2 w = wrow[p];          // W[k][4p..4p+3]
        fma2(acc[2 * p],     hh, w.x);
        fma2(acc[2 * p + 1], hh, w.y);
    }
}

__global__ __launch_bounds__(256, 1)
void k_child(const int* __restrict__ cfi, const int* __restrict__ child_cat,
             const float* __restrict__ child_num, const float* __restrict__ emb_child,
             const float* __restrict__ W, const float* __restrict__ bias,
             float* __restrict__ out) {
    extern __shared__ float Wt[];   // [KDIM][WPAD]

    // Transpose W [32][1152] -> Wt [1152][36]; gmem reads fully coalesced.
    for (int i = threadIdx.x; i < OUTD * KDIM; i += 256) {
        int o = i / KDIM;
        int k = i - o * KDIM;
        Wt[k * WPAD + o] = W[i];
    }
    __syncthreads();

    int row = blockIdx.x * 256 + threadIdx.x;   // < 131072 exactly
    int g = cfi[row];                            // global child row id

    unsigned long long acc[16];
#pragma unroll
    for (int p = 0; p < 16; ++p) {
        float2 bb = ((const float2*)bias)[p];
        acc[p] = pack2(bb.x, bb.y);
    }

    // --- categorical part: gather child_cat THROUGH cfi (bug fix), then embed ---
    int cats[CC];
    {
        const int4* crow4 = (const int4*)(child_cat + (size_t)g * CC);
#pragma unroll
        for (int q = 0; q < CC / 4; ++q) {
            int4 c4 = crow4[q];
            cats[4 * q + 0] = c4.x;
            cats[4 * q + 1] = c4.y;
            cats[4 * q + 2] = c4.z;
            cats[4 * q + 3] = c4.w;
        }
    }
#pragma unroll 1
    for (int c = 0; c < CC; ++c) {
        int v = cats[c];
        const float4* e = (const float4*)(emb_child + ((size_t)c * VOCAB + v) * DIM);
#pragma unroll 4
        for (int j = 0; j < 16; ++j) {
            float4 h4 = e[j];
            int kb = c * DIM + j * 4;
            fma_row(acc, Wt, kb + 0, h4.x);
            fma_row(acc, Wt, kb + 1, h4.y);
            fma_row(acc, Wt, kb + 2, h4.z);
            fma_row(acc, Wt, kb + 3, h4.w);
        }
    }

    // --- numeric part: gather + BN + FMA ---
    const float4* nrow = (const float4*)(child_num + (size_t)g * NC);
    const float4* A4  = (const float4*)g_a_c;
    const float4* S4  = (const float4*)g_s_c;
#pragma unroll 4
    for (int j = 0; j < NC / 4; ++j) {
        float4 x = nrow[j];
        float4 a = A4[j];
        float4 s = S4[j];
        float h0 = fmaf(x.x, a.x, s.x);
        float h1 = fmaf(x.y, a.y, s.y);
        float h2 = fmaf(x.z, a.z, s.z);
        float h3 = fmaf(x.w, a.w, s.w);
        int kb = CC * DIM + j * 4;
        fma_row(acc, Wt, kb + 0, h0);
        fma_row(acc, Wt, kb + 1, h1);
        fma_row(acc, Wt, kb + 2, h2);
        fma_row(acc, Wt, kb + 3, h3);
    }

    // --- ReLU, then mean over 16 consecutive rows (one root) via shfl ---
    float r[32];
#pragma unroll
    for (int p = 0; p < 16; ++p) {
        float lo, hi;
        unpack2(acc[p], lo, hi);
        r[2 * p]     = fmaxf(lo, 0.f);
        r[2 * p + 1] = fmaxf(hi, 0.f);
    }
#pragma unroll
    for (int s = 1; s < 16; s <<= 1) {
#pragma unroll
        for (int i = 0; i < 32; ++i)
            r[i] += __shfl_xor_sync(0xffffffffu, r[i], s);
    }
    int lane = threadIdx.x & 31;
    int sub  = lane & 15;
    int root = row >> 4;
    float2 val;
    val.x = r[2 * sub]     * (1.0f / (float)KFAN);
    val.y = r[2 * sub + 1] * (1.0f / (float)KFAN);
    *(float2*)(out + (size_t)root * OUTCOLS + CR * DIM + NR + 2 * sub) = val;
}

// ---------------- launch ----------------
extern "C" void kernel_launch(void* const* d_in, const int* in_sizes, int n_in,
                              void* d_out, int out_size) {
    const int *idx = nullptr, *cfi = nullptr, *root_cat = nullptr, *child_cat = nullptr;
    const float *root_num = nullptr, *child_num = nullptr;
    const float *emb_root = nullptr, *emb_child = nullptr;
    const float *W = nullptr, *bias = nullptr;
    const float *gamma_r = nullptr, *beta_r = nullptr, *gamma_c = nullptr, *beta_c = nullptr;

    for (int i = 0; i < n_in; ++i) {
        long long s = in_sizes[i];
        void* p = d_in[i];
        switch (s) {
            case 8192:      idx = (const int*)p; break;
            case 131072:    cfi = (const int*)p; break;
            case 1600000:   root_cat  = (const int*)p; break;
            case 8000000:   child_cat = (const int*)p; break;
            case 12800000:  root_num  = (const float*)p; break;
            case 64000000:  child_num = (const float*)p; break;
            case 25600000:  emb_root  = (const float*)p; break;
            case 51200000:  emb_child = (const float*)p; break;
            case 36864:     W = (const float*)p; break;
            case 32:        bias = (const float*)p; break;
            case 64:
                if (!gamma_r) gamma_r = (const float*)p; else beta_r = (const float*)p;
                break;
            case 128:
                if (!gamma_c) gamma_c = (const float*)p; else beta_c = (const float*)p;
                break;
            default: break;
        }
    }

    float* out = (float*)d_out;

    k_reset<<<1, 256>>>();
    k_stats_child<<<NCHILD / 256, 128>>>(cfi, child_num);
    k_stats_root<<<B_ROOT / 256, 64>>>(idx, root_num);
    k_finalize<<<1, 128>>>(gamma_c, beta_c, gamma_r, beta_r);
    k_root<<<B_ROOT / 8, 256>>>(idx, root_cat, root_num, emb_root, out);

    const int smem = KDIM * WPAD * (int)sizeof(float);   // 165888 B
    cudaFuncSetAttribute(k_child, cudaFuncAttributeMaxDynamicSharedMemorySize, smem);
    k_child<<<NCHILD / 256, 256, smem>>>(cfi, child_cat, child_num, emb_child, W, bias, out);
}

// round 4
// speedup vs baseline: 1.2968x; 1.2968x over previous
#include <cuda_runtime.h>
#include <cstdint>

#define B_ROOT   8192
#define KFAN     16
#define NCHILD   (B_ROOT * KFAN)     // 131072
#define VOCAB    50000
#define DIM      64
#define CR       8
#define NR       64
#define CC       16
#define NC       128
#define OUTD     32
#define KDIM     (CC * DIM + NC)     // 1152
#define OUTCOLS  (CR * DIM + NR + OUTD)  // 608
#define EPSBN    1e-5f

// ---------------- scratch (device globals; allocation-free) ----------------
__device__ __align__(16) double g_sum_c[NC];
__device__ __align__(16) double g_ss_c [NC];
__device__ __align__(16) double g_sum_r[NR];
__device__ __align__(16) double g_ss_r [NR];
__device__ __align__(16) float g_a_c[NC];       // gamma * rsqrt(var+eps)
__device__ __align__(16) float g_s_c[NC];       // beta - mean * a
__device__ __align__(16) float g_a_r[NR];
__device__ __align__(16) float g_s_r[NR];
__device__ __align__(16) float g_wn[NC * OUTD]; // BN-folded numeric weight [k][o]
__device__ __align__(16) float g_bp[OUTD];      // bias + shift @ Wn^T
// Precomputed categorical projection: proj[c][v][o] = emb_child[c,v,:] @ W[:,c*64:+64]^T
__device__ __align__(256) float g_proj[CC * VOCAB * OUTD];   // 102.4 MB

// ---------------- packed f32x2 helpers ----------------
__device__ __forceinline__ unsigned long long pack2(float a, float b) {
    unsigned long long r;
    asm("mov.b64 %0, {%1, %2};" : "=l"(r) : "f"(a), "f"(b));
    return r;
}
__device__ __forceinline__ void unpack2(unsigned long long v, float& lo, float& hi) {
    asm("mov.b64 {%0, %1}, %2;" : "=f"(lo), "=f"(hi) : "l"(v));
}
__device__ __forceinline__ void fma2(unsigned long long& d, unsigned long long a, unsigned long long b) {
    asm("fma.rn.f32x2 %0, %1, %2, %0;" : "+l"(d) : "l"(a), "l"(b));
}
__device__ __forceinline__ void add2(unsigned long long& d, unsigned long long a) {
    asm("add.rn.f32x2 %0, %0, %1;" : "+l"(d) : "l"(a));
}

// ---------------- kernel 0: reset stat accumulators ----------------
__global__ void k_reset() {
    int t = threadIdx.x;
    if (t < NC) { g_sum_c[t] = 0.0; g_ss_c[t] = 0.0; }
    if (t < NR) { g_sum_r[t] = 0.0; g_ss_r[t] = 0.0; }
}

// ---------------- kernel 1: child BN stats (MLP-8 unrolled) ----------------
// grid 1024, block 128 (thread = column), 128 rows per block
__global__ void k_stats_child(const int* __restrict__ cfi, const float* __restrict__ child_num) {
    int col = threadIdx.x;
    int r0 = blockIdx.x * 128;
    float s[8], ss[8];
#pragma unroll
    for (int u = 0; u < 8; ++u) { s[u] = 0.f; ss[u] = 0.f; }
    for (int r = r0; r < r0 + 128; r += 8) {
        float x[8];
#pragma unroll
        for (int u = 0; u < 8; ++u) {
            int g = __ldg(&cfi[r + u]);
            x[u] = __ldg(&child_num[(size_t)g * NC + col]);
        }
#pragma unroll
        for (int u = 0; u < 8; ++u) { s[u] += x[u]; ss[u] += x[u] * x[u]; }
    }
    float st = (s[0]+s[1])+(s[2]+s[3])+((s[4]+s[5])+(s[6]+s[7]));
    float sst = (ss[0]+ss[1])+(ss[2]+ss[3])+((ss[4]+ss[5])+(ss[6]+ss[7]));
    atomicAdd(&g_sum_c[col], (double)st);
    atomicAdd(&g_ss_c[col], (double)sst);
}

// ---------------- kernel 2: root BN stats ----------------
__global__ void k_stats_root(const int* __restrict__ idx, const float* __restrict__ root_num) {
    int col = threadIdx.x;
    int r0 = blockIdx.x * 128;
    float s[8], ss[8];
#pragma unroll
    for (int u = 0; u < 8; ++u) { s[u] = 0.f; ss[u] = 0.f; }
    for (int r = r0; r < r0 + 128; r += 8) {
        float x[8];
#pragma unroll
        for (int u = 0; u < 8; ++u) {
            int g = __ldg(&idx[r + u]);
            x[u] = __ldg(&root_num[(size_t)g * NR + col]);
        }
#pragma unroll
        for (int u = 0; u < 8; ++u) { s[u] += x[u]; ss[u] += x[u] * x[u]; }
    }
    float st = (s[0]+s[1])+(s[2]+s[3])+((s[4]+s[5])+(s[6]+s[7]));
    float sst = (ss[0]+ss[1])+(ss[2]+ss[3])+((ss[4]+ss[5])+(ss[6]+ss[7]));
    atomicAdd(&g_sum_r[col], (double)st);
    atomicAdd(&g_ss_r[col], (double)sst);
}

// ---------------- kernel 3: finalize BN + fold numeric weights ----------------
__global__ void k_finalize(const float* __restrict__ gamma_c, const float* __restrict__ beta_c,
                           const float* __restrict__ gamma_r, const float* __restrict__ beta_r,
                           const float* __restrict__ W, const float* __restrict__ bias) {
    int t = threadIdx.x;
    if (t < NC) {
        double m = g_sum_c[t] * (1.0 / (double)NCHILD);
        double v = g_ss_c[t] * (1.0 / (double)NCHILD) - m * m;
        float a = gamma_c[t] * rsqrtf((float)v + EPSBN);
        g_a_c[t] = a;
        g_s_c[t] = beta_c[t] - (float)m * a;
    }
    if (t < NR) {
        double m = g_sum_r[t] * (1.0 / (double)B_ROOT);
        double v = g_ss_r[t] * (1.0 / (double)B_ROOT) - m * m;
        float a = gamma_r[t] * rsqrtf((float)v + EPSBN);
        g_a_r[t] = a;
        g_s_r[t] = beta_r[t] - (float)m * a;
    }
    __syncthreads();
    // fold: g_wn[k][o] = a_c[k] * W[o][CC*DIM + k]
    for (int i = t; i < NC * OUTD; i += 128) {
        int k = i >> 5, o = i & 31;
        g_wn[i] = g_a_c[k] * W[(size_t)o * KDIM + CC * DIM + k];
    }
    // g_bp[o] = bias[o] + sum_k s_c[k] * W[o][CC*DIM + k]
    if (t < OUTD) {
        float acc = bias[t];
        for (int k = 0; k < NC; ++k)
            acc += g_s_c[k] * W[(size_t)t * KDIM + CC * DIM + k];
        g_bp[t] = acc;
    }
}

// ---------------- kernel 4: build proj table ----------------
// proj[c][v][o] = sum_d emb_child[c][v][d] * W[o][c*64 + d]
// grid (CC, ceil(VOCAB/32)), block 256. 32 rows/block; thread computes 4 (r,o).
#define PROJ_ROWS 32
__global__ __launch_bounds__(256)
void k_proj(const float* __restrict__ emb_child, const float* __restrict__ W) {
    __shared__ float Ws[DIM][OUTD + 1];       // W[o][c*64+d] -> Ws[d][o]
    __shared__ float Es[PROJ_ROWS][DIM];      // emb rows
    int c = blockIdx.x;
    int v0 = blockIdx.y * PROJ_ROWS;
    int t = threadIdx.x;

    // load W slice: 2048 elems, coalesced in d
    for (int i = t; i < DIM * OUTD; i += 256) {
        int o = i >> 6, d = i & 63;
        Ws[d][o] = W[(size_t)o * KDIM + c * DIM + d];
    }
    // load 32 emb rows (guard tail)
    for (int i = t; i < PROJ_ROWS * DIM; i += 256) {
        int r = i >> 6, d = i & 63;
        int v = v0 + r;
        Es[r][d] = (v < VOCAB) ? emb_child[((size_t)c * VOCAB + v) * DIM + d] : 0.f;
    }
    __syncthreads();

    int o = t & 31;
    int rb = t >> 5;                 // 0..7
#pragma unroll
    for (int it = 0; it < 4; ++it) {
        int r = rb + it * 8;
        int v = v0 + r;
        if (v >= VOCAB) continue;
        float sum = 0.f;
#pragma unroll
        for (int d = 0; d < DIM; ++d)
            sum = fmaf(Es[r][d], Ws[d][o], sum);
        g_proj[((size_t)c * VOCAB + v) * OUTD + o] = sum;
    }
}

// ---------------- kernel 5: root output (emb gather + BN nums) ----------------
__global__ void k_root(const int* __restrict__ idx, const int* __restrict__ root_cat,
                       const float* __restrict__ root_num, const float* __restrict__ emb_root,
                       float* __restrict__ out) {
    int warp = (blockIdx.x * blockDim.x + threadIdx.x) >> 5;
    int lane = threadIdx.x & 31;
    if (warp >= B_ROOT) return;
    int g = idx[warp];
    const int* cr = root_cat + (size_t)g * CR;
    float* orow = out + (size_t)warp * OUTCOLS;
#pragma unroll
    for (int c = 0; c < CR; ++c) {
        int v = cr[c];
        const float2* e = (const float2*)(emb_root + ((size_t)c * VOCAB + v) * DIM);
        *(float2*)(orow + c * DIM + lane * 2) = e[lane];
    }
    float2 x  = *(const float2*)(root_num + (size_t)g * NR + lane * 2);
    float2 a  = ((const float2*)g_a_r)[lane];
    float2 sh = ((const float2*)g_s_r)[lane];
    float2 y;
    y.x = fmaf(x.x, a.x, sh.x);
    y.y = fmaf(x.y, a.y, sh.y);
    *(float2*)(orow + CR * DIM + lane * 2) = y;
}

// ---------------- kernel 6: fused child (proj gather + folded numeric + mean) --------
__global__ __launch_bounds__(256)
void k_child(const int* __restrict__ cfi, const int* __restrict__ child_cat,
             const float* __restrict__ child_num, float* __restrict__ out) {
    __shared__ float Wn[NC * OUTD];   // 16 KB, [k][o]
    for (int i = threadIdx.x; i < NC * OUTD; i += 256)
        Wn[i] = g_wn[i];
    __syncthreads();

    int row = blockIdx.x * 256 + threadIdx.x;   // exactly NCHILD threads
    int g = cfi[row];

    unsigned long long acc[16];
#pragma unroll
    for (int p = 0; p < 16; ++p) {
        float2 bb = ((const float2*)g_bp)[p];
        acc[p] = pack2(bb.x, bb.y);
    }

    // --- categorical: 16 gathers of precomputed 32-float proj rows, add ---
    int cats[CC];
    {
        const int4* crow4 = (const int4*)(child_cat + (size_t)g * CC);
#pragma unroll
        for (int q = 0; q < CC / 4; ++q) {
            int4 c4 = crow4[q];
            cats[4 * q + 0] = c4.x;
            cats[4 * q + 1] = c4.y;
            cats[4 * q + 2] = c4.z;
            cats[4 * q + 3] = c4.w;
        }
    }
#pragma unroll 4
    for (int c = 0; c < CC; ++c) {
        const float4* p = (const float4*)(g_proj + ((size_t)c * VOCAB + cats[c]) * OUTD);
        float4 t0 = p[0], t1 = p[1], t2 = p[2], t3 = p[3];
        float4 t4 = p[4], t5 = p[5], t6 = p[6], t7 = p[7];
        add2(acc[0],  pack2(t0.x, t0.y)); add2(acc[1],  pack2(t0.z, t0.w));
        add2(acc[2],  pack2(t1.x, t1.y)); add2(acc[3],  pack2(t1.z, t1.w));
        add2(acc[4],  pack2(t2.x, t2.y)); add2(acc[5],  pack2(t2.z, t2.w));
        add2(acc[6],  pack2(t3.x, t3.y)); add2(acc[7],  pack2(t3.z, t3.w));
        add2(acc[8],  pack2(t4.x, t4.y)); add2(acc[9],  pack2(t4.z, t4.w));
        add2(acc[10], pack2(t5.x, t5.y)); add2(acc[11], pack2(t5.z, t5.w));
        add2(acc[12], pack2(t6.x, t6.y)); add2(acc[13], pack2(t6.z, t6.w));
        add2(acc[14], pack2(t7.x, t7.y)); add2(acc[15], pack2(t7.z, t7.w));
    }

    // --- numeric: x @ (a ⊙ Wn)^T   (shift folded into g_bp) ---
    const float4* nrow = (const float4*)(child_num + (size_t)g * NC);
#pragma unroll 4
    for (int j = 0; j < NC / 4; ++j) {
        float4 x = nrow[j];
        const float h[4] = {x.x, x.y, x.z, x.w};
#pragma unroll
        for (int q = 0; q < 4; ++q) {
            unsigned long long hh = pack2(h[q], h[q]);
            const ulonglong2* wrow = (const ulonglong2*)(Wn + (j * 4 + q) * OUTD);
#pragma unroll
            for (int p = 0; p < 8; ++p) {
                ulonglong2 w = wrow[p];
                fma2(acc[2 * p],     hh, w.x);
                fma2(acc[2 * p + 1], hh, w.y);
            }
        }
    }

    // --- ReLU, then mean over 16 consecutive rows (one root) via shfl ---
    float r[32];
#pragma unroll
    for (int p = 0; p < 16; ++p) {
        float lo, hi;
        unpack2(acc[p], lo, hi);
        r[2 * p]     = fmaxf(lo, 0.f);
        r[2 * p + 1] = fmaxf(hi, 0.f);
    }
#pragma unroll
    for (int s = 1; s < 16; s <<= 1) {
#pragma unroll
        for (int i = 0; i < 32; ++i)
            r[i] += __shfl_xor_sync(0xffffffffu, r[i], s);
    }
    int lane = threadIdx.x & 31;
    int sub  = lane & 15;
    int root = row >> 4;
    float2 val;
    val.x = r[2 * sub]     * (1.0f / (float)KFAN);
    val.y = r[2 * sub + 1] * (1.0f / (float)KFAN);
    *(float2*)(out + (size_t)root * OUTCOLS + CR * DIM + NR + 2 * sub) = val;
}

// ---------------- launch ----------------
extern "C" void kernel_launch(void* const* d_in, const int* in_sizes, int n_in,
                              void* d_out, int out_size) {
    const int *idx = nullptr, *cfi = nullptr, *root_cat = nullptr, *child_cat = nullptr;
    const float *root_num = nullptr, *child_num = nullptr;
    const float *emb_root = nullptr, *emb_child = nullptr;
    const float *W = nullptr, *bias = nullptr;
    const float *gamma_r = nullptr, *beta_r = nullptr, *gamma_c = nullptr, *beta_c = nullptr;

    for (int i = 0; i < n_in; ++i) {
        long long s = in_sizes[i];
        void* p = d_in[i];
        switch (s) {
            case 8192:      idx = (const int*)p; break;
            case 131072:    cfi = (const int*)p; break;
            case 1600000:   root_cat  = (const int*)p; break;
            case 8000000:   child_cat = (const int*)p; break;
            case 12800000:  root_num  = (const float*)p; break;
            case 64000000:  child_num = (const float*)p; break;
            case 25600000:  emb_root  = (const float*)p; break;
            case 51200000:  emb_child = (const float*)p; break;
            case 36864:     W = (const float*)p; break;
            case 32:        bias = (const float*)p; break;
            case 64:
                if (!gamma_r) gamma_r = (const float*)p; else beta_r = (const float*)p;
                break;
            case 128:
                if (!gamma_c) gamma_c = (const float*)p; else beta_c = (const float*)p;
                break;
            default: break;
        }
    }

    float* out = (float*)d_out;

    k_reset<<<1, 256>>>();
    k_stats_child<<<NCHILD / 128, 128>>>(cfi, child_num);
    k_stats_root<<<B_ROOT / 128, 64>>>(idx, root_num);
    k_finalize<<<1, 128>>>(gamma_c, beta_c, gamma_r, beta_r, W, bias);

    dim3 pgrid(CC, (VOCAB + PROJ_ROWS - 1) / PROJ_ROWS);
    k_proj<<<pgrid, 256>>>(emb_child, W);

    k_root<<<B_ROOT / 8, 256>>>(idx, root_cat, root_num, emb_root, out);
    k_child<<<NCHILD / 256, 256>>>(cfi, child_cat, child_num, out);
}

// round 6
// speedup vs baseline: 2.0367x; 1.5705x over previous
#include <cuda_runtime.h>
#include <cstdint>

#define B_ROOT   8192
#define KFAN     16
#define NCHILD   (B_ROOT * KFAN)     // 131072
#define VOCAB    50000
#define DIM      64
#define CR       8
#define NR       64
#define CC       16
#define NC       128
#define OUTD     32
#define KDIM     (CC * DIM + NC)     // 1152
#define OUTCOLS  (CR * DIM + NR + OUTD)  // 608
#define EPSBN    1e-5f

// ---------------- scratch (device globals; allocation-free) ----------------
__device__ __align__(16) double g_sum_c[NC];
__device__ __align__(16) double g_ss_c [NC];
__device__ __align__(16) double g_sum_r[NR];
__device__ __align__(16) double g_ss_r [NR];
__device__ __align__(16) float g_a_c[NC];       // gamma * rsqrt(var+eps)
__device__ __align__(16) float g_s_c[NC];       // beta - mean * a
__device__ __align__(16) float g_a_r[NR];
__device__ __align__(16) float g_s_r[NR];
__device__ __align__(16) float g_wn[NC * OUTD]; // BN-folded numeric weight [k][o]
__device__ __align__(16) float g_bp[OUTD];      // bias + shift @ Wn^T
// Precomputed categorical projection: proj[c][v][o] = emb_child[c,v,:] @ W[:,c*64:+64]^T
__device__ __align__(256) float g_proj[CC * VOCAB * OUTD];   // 102.4 MB

// ---------------- packed f32x2 helpers ----------------
__device__ __forceinline__ unsigned long long pack2(float a, float b) {
    unsigned long long r;
    asm("mov.b64 %0, {%1, %2};" : "=l"(r) : "f"(a), "f"(b));
    return r;
}
__device__ __forceinline__ void unpack2(unsigned long long v, float& lo, float& hi) {
    asm("mov.b64 {%0, %1}, %2;" : "=f"(lo), "=f"(hi) : "l"(v));
}
__device__ __forceinline__ void fma2(unsigned long long& d, unsigned long long a, unsigned long long b) {
    asm("fma.rn.f32x2 %0, %1, %2, %0;" : "+l"(d) : "l"(a), "l"(b));
}
__device__ __forceinline__ void add2(unsigned long long& d, unsigned long long a) {
    asm("add.rn.f32x2 %0, %0, %1;" : "+l"(d) : "l"(a));
}

// ---------------- kernel 0: reset stat accumulators ----------------
__global__ void k_reset() {
    int t = threadIdx.x;
    if (t < NC) { g_sum_c[t] = 0.0; g_ss_c[t] = 0.0; }
    if (t < NR) { g_sum_r[t] = 0.0; g_ss_r[t] = 0.0; }
}

// ---------------- kernel 1: child BN stats (smem idx stage + MLP-8) ----------------
// grid 1024, block 128 (thread = column), 128 rows per block
__global__ void k_stats_child(const int* __restrict__ cfi, const float* __restrict__ child_num) {
    __shared__ int rid[128];
    int t = threadIdx.x;
    int r0 = blockIdx.x * 128;
    rid[t] = cfi[r0 + t];          // 128 threads stage 128 rows
    __syncthreads();
    int col = t;
    float s[8], ss[8];
#pragma unroll
    for (int u = 0; u < 8; ++u) { s[u] = 0.f; ss[u] = 0.f; }
    for (int r = 0; r < 128; r += 8) {
        float x[8];
#pragma unroll
        for (int u = 0; u < 8; ++u) {
            int g = rid[r + u];
            x[u] = __ldg(&child_num[(size_t)g * NC + col]);
        }
#pragma unroll
        for (int u = 0; u < 8; ++u) { s[u] += x[u]; ss[u] += x[u] * x[u]; }
    }
    float st = (s[0]+s[1])+(s[2]+s[3])+((s[4]+s[5])+(s[6]+s[7]));
    float sst = (ss[0]+ss[1])+(ss[2]+ss[3])+((ss[4]+ss[5])+(ss[6]+ss[7]));
    atomicAdd(&g_sum_c[col], (double)st);
    atomicAdd(&g_ss_c[col], (double)sst);
}

// ---------------- kernel 2: root BN stats (64 threads -> stage 2 idx each) -------
__global__ void k_stats_root(const int* __restrict__ idx, const float* __restrict__ root_num) {
    __shared__ int rid[128];
    int t = threadIdx.x;                 // blockDim.x == 64
    int r0 = blockIdx.x * 128;
    rid[t]      = idx[r0 + t];           // BUG FIX: 64 threads must stage all
    rid[t + 64] = idx[r0 + t + 64];      // 128 rows (was: only first 64 written)
    __syncthreads();
    int col = t;
    float s[8], ss[8];
#pragma unroll
    for (int u = 0; u < 8; ++u) { s[u] = 0.f; ss[u] = 0.f; }
    for (int r = 0; r < 128; r += 8) {
        float x[8];
#pragma unroll
        for (int u = 0; u < 8; ++u) {
            int g = rid[r + u];
            x[u] = __ldg(&root_num[(size_t)g * NR + col]);
        }
#pragma unroll
        for (int u = 0; u < 8; ++u) { s[u] += x[u]; ss[u] += x[u] * x[u]; }
    }
    float st = (s[0]+s[1])+(s[2]+s[3])+((s[4]+s[5])+(s[6]+s[7]));
    float sst = (ss[0]+ss[1])+(ss[2]+ss[3])+((ss[4]+ss[5])+(ss[6]+ss[7]));
    atomicAdd(&g_sum_r[col], (double)st);
    atomicAdd(&g_ss_r[col], (double)sst);
}

// ---------------- kernel 3: finalize BN + fold numeric weights (parallel) ----------------
__global__ void k_finalize(const float* __restrict__ gamma_c, const float* __restrict__ beta_c,
                           const float* __restrict__ gamma_r, const float* __restrict__ beta_r,
                           const float* __restrict__ W, const float* __restrict__ bias) {
    int t = threadIdx.x;
    if (t < NC) {
        double m = g_sum_c[t] * (1.0 / (double)NCHILD);
        double v = g_ss_c[t] * (1.0 / (double)NCHILD) - m * m;
        float a = gamma_c[t] * rsqrtf((float)v + EPSBN);
        g_a_c[t] = a;
        g_s_c[t] = beta_c[t] - (float)m * a;
    }
    if (t < NR) {
        double m = g_sum_r[t] * (1.0 / (double)B_ROOT);
        double v = g_ss_r[t] * (1.0 / (double)B_ROOT) - m * m;
        float a = gamma_r[t] * rsqrtf((float)v + EPSBN);
        g_a_r[t] = a;
        g_s_r[t] = beta_r[t] - (float)m * a;
    }
    __syncthreads();
    // fold: g_wn[k][o] = a_c[k] * W[o][CC*DIM + k]
    for (int i = t; i < NC * OUTD; i += 128) {
        int k = i >> 5, o = i & 31;
        g_wn[i] = g_a_c[k] * W[(size_t)o * KDIM + CC * DIM + k];
    }
    // g_bp[o] = bias[o] + sum_k s_c[k] * W[o][CC*DIM + k]  (4 threads per o)
    {
        int o = t >> 2;          // 0..31
        int sl = t & 3;
        float acc = 0.f;
        for (int k = sl; k < NC; k += 4)
            acc += g_s_c[k] * W[(size_t)o * KDIM + CC * DIM + k];
        acc += __shfl_xor_sync(0xffffffffu, acc, 1);
        acc += __shfl_xor_sync(0xffffffffu, acc, 2);
        if (sl == 0) g_bp[o] = acc + bias[o];
    }
}

// ---------------- kernel 4: build proj table (f32x2, register accs) ----------------
// proj[c][v][o] = sum_d emb_child[c][v][d] * W[o][c*64 + d]
// grid (CC, ceil(VOCAB/256)), block 256; one thread per vocab row.
#define PROJ_ROWS 256
#define EPITCH    (DIM + 1)          // 65 -> conflict-free column reads
__global__ __launch_bounds__(256)
void k_proj(const float* __restrict__ emb_child, const float* __restrict__ W) {
    extern __shared__ float sm[];
    float* Er = sm;                          // [PROJ_ROWS][EPITCH]
    float* Ws = sm + PROJ_ROWS * EPITCH;     // [DIM][OUTD]
    int c = blockIdx.x;
    int v0 = blockIdx.y * PROJ_ROWS;
    int t = threadIdx.x;

    // stage W slice: Ws[d][o] = W[o][c*64+d]; reads coalesced in d
    for (int i = t; i < DIM * OUTD; i += 256) {
        int o = i >> 6, d = i & 63;
        Ws[d * OUTD + o] = W[(size_t)o * KDIM + c * DIM + d];
    }
    // stage emb rows (coalesced read, conflict-free write)
    for (int i = t; i < PROJ_ROWS * DIM; i += 256) {
        int r = i >> 6, d = i & 63;
        int v = v0 + r;
        Er[r * EPITCH + d] = (v < VOCAB) ? emb_child[((size_t)c * VOCAB + v) * DIM + d] : 0.f;
    }
    __syncthreads();

    int v = v0 + t;
    unsigned long long acc[16];
#pragma unroll
    for (int j = 0; j < 16; ++j) acc[j] = pack2(0.f, 0.f);

    const float* er = Er + t * EPITCH;
#pragma unroll 8
    for (int d = 0; d < DIM; ++d) {
        float e = er[d];                      // lanes stride 65 words -> conflict-free
        unsigned long long ee = pack2(e, e);
        const ulonglong2* wr = (const ulonglong2*)(Ws + d * OUTD);   // broadcast
#pragma unroll
        for (int p = 0; p < 8; ++p) {
            ulonglong2 w = wr[p];             // outputs 4p..4p+3
            fma2(acc[2 * p],     ee, w.x);
            fma2(acc[2 * p + 1], ee, w.y);
        }
    }

    if (v < VOCAB) {
        ulonglong2* out = (ulonglong2*)(g_proj + ((size_t)c * VOCAB + v) * OUTD);
#pragma unroll
        for (int p = 0; p < 8; ++p) {
            ulonglong2 o2; o2.x = acc[2 * p]; o2.y = acc[2 * p + 1];
            out[p] = o2;
        }
    }
}

// ---------------- kernel 5: root output (emb gather + BN nums) ----------------
__global__ void k_root(const int* __restrict__ idx, const int* __restrict__ root_cat,
                       const float* __restrict__ root_num, const float* __restrict__ emb_root,
                       float* __restrict__ out) {
    int warp = (blockIdx.x * blockDim.x + threadIdx.x) >> 5;
    int lane = threadIdx.x & 31;
    if (warp >= B_ROOT) return;
    int g = idx[warp];
    const int* cr = root_cat + (size_t)g * CR;
    float* orow = out + (size_t)warp * OUTCOLS;
#pragma unroll
    for (int c = 0; c < CR; ++c) {
        int v = cr[c];
        const float2* e = (const float2*)(emb_root + ((size_t)c * VOCAB + v) * DIM);
        *(float2*)(orow + c * DIM + lane * 2) = e[lane];
    }
    float2 x  = *(const float2*)(root_num + (size_t)g * NR + lane * 2);
    float2 a  = ((const float2*)g_a_r)[lane];
    float2 sh = ((const float2*)g_s_r)[lane];
    float2 y;
    y.x = fmaf(x.x, a.x, sh.x);
    y.y = fmaf(x.y, a.y, sh.y);
    *(float2*)(orow + CR * DIM + lane * 2) = y;
}

// ---------------- kernel 6: fused child (proj gather + folded numeric + mean) --------
__global__ __launch_bounds__(256)
void k_child(const int* __restrict__ cfi, const int* __restrict__ child_cat,
             const float* __restrict__ child_num, float* __restrict__ out) {
    __shared__ float Wn[NC * OUTD];   // 16 KB, [k][o]
    for (int i = threadIdx.x; i < NC * OUTD; i += 256)
        Wn[i] = g_wn[i];
    __syncthreads();

    int row = blockIdx.x * 256 + threadIdx.x;   // exactly NCHILD threads
    int g = cfi[row];

    unsigned long long acc[16];
#pragma unroll
    for (int p = 0; p < 16; ++p) {
        float2 bb = ((const float2*)g_bp)[p];
        acc[p] = pack2(bb.x, bb.y);
    }

    // --- categorical: 16 gathers of precomputed 32-float proj rows, add ---
    int cats[CC];
    {
        const int4* crow4 = (const int4*)(child_cat + (size_t)g * CC);
#pragma unroll
        for (int q = 0; q < CC / 4; ++q) {
            int4 c4 = crow4[q];
            cats[4 * q + 0] = c4.x;
            cats[4 * q + 1] = c4.y;
            cats[4 * q + 2] = c4.z;
            cats[4 * q + 3] = c4.w;
        }
    }
#pragma unroll 4
    for (int c = 0; c < CC; ++c) {
        const float4* p = (const float4*)(g_proj + ((size_t)c * VOCAB + cats[c]) * OUTD);
        float4 t0 = p[0], t1 = p[1], t2 = p[2], t3 = p[3];
        float4 t4 = p[4], t5 = p[5], t6 = p[6], t7 = p[7];
        add2(acc[0],  pack2(t0.x, t0.y)); add2(acc[1],  pack2(t0.z, t0.w));
        add2(acc[2],  pack2(t1.x, t1.y)); add2(acc[3],  pack2(t1.z, t1.w));
        add2(acc[4],  pack2(t2.x, t2.y)); add2(acc[5],  pack2(t2.z, t2.w));
        add2(acc[6],  pack2(t3.x, t3.y)); add2(acc[7],  pack2(t3.z, t3.w));
        add2(acc[8],  pack2(t4.x, t4.y)); add2(acc[9],  pack2(t4.z, t4.w));
        add2(acc[10], pack2(t5.x, t5.y)); add2(acc[11], pack2(t5.z, t5.w));
        add2(acc[12], pack2(t6.x, t6.y)); add2(acc[13], pack2(t6.z, t6.w));
        add2(acc[14], pack2(t7.x, t7.y)); add2(acc[15], pack2(t7.z, t7.w));
    }

    // --- numeric: x @ (a ⊙ Wn)^T   (shift folded into g_bp) ---
    const float4* nrow = (const float4*)(child_num + (size_t)g * NC);
#pragma unroll 4
    for (int j = 0; j < NC / 4; ++j) {
        float4 x = nrow[j];
        const float h[4] = {x.x, x.y, x.z, x.w};
#pragma unroll
        for (int q = 0; q < 4; ++q) {
            unsigned long long hh = pack2(h[q], h[q]);
            const ulonglong2* wrow = (const ulonglong2*)(Wn + (j * 4 + q) * OUTD);
#pragma unroll
            for (int p = 0; p < 8; ++p) {
                ulonglong2 w = wrow[p];
                fma2(acc[2 * p],     hh, w.x);
                fma2(acc[2 * p + 1], hh, w.y);
            }
        }
    }

    // --- ReLU, then mean over 16 consecutive rows (one root) via shfl ---
    float r[32];
#pragma unroll
    for (int p = 0; p < 16; ++p) {
        float lo, hi;
        unpack2(acc[p], lo, hi);
        r[2 * p]     = fmaxf(lo, 0.f);
        r[2 * p + 1] = fmaxf(hi, 0.f);
    }
#pragma unroll
    for (int s = 1; s < 16; s <<= 1) {
#pragma unroll
        for (int i = 0; i < 32; ++i)
            r[i] += __shfl_xor_sync(0xffffffffu, r[i], s);
    }
    int lane = threadIdx.x & 31;
    int sub  = lane & 15;
    int root = row >> 4;
    float2 val;
    val.x = r[2 * sub]     * (1.0f / (float)KFAN);
    val.y = r[2 * sub + 1] * (1.0f / (float)KFAN);
    *(float2*)(out + (size_t)root * OUTCOLS + CR * DIM + NR + 2 * sub) = val;
}

// ---------------- launch ----------------
extern "C" void kernel_launch(void* const* d_in, const int* in_sizes, int n_in,
                              void* d_out, int out_size) {
    const int *idx = nullptr, *cfi = nullptr, *root_cat = nullptr, *child_cat = nullptr;
    const float *root_num = nullptr, *child_num = nullptr;
    const float *emb_root = nullptr, *emb_child = nullptr;
    const float *W = nullptr, *bias = nullptr;
    const float *gamma_r = nullptr, *beta_r = nullptr, *gamma_c = nullptr, *beta_c = nullptr;

    for (int i = 0; i < n_in; ++i) {
        long long s = in_sizes[i];
        void* p = d_in[i];
        switch (s) {
            case 8192:      idx = (const int*)p; break;
            case 131072:    cfi = (const int*)p; break;
            case 1600000:   root_cat  = (const int*)p; break;
            case 8000000:   child_cat = (const int*)p; break;
            case 12800000:  root_num  = (const float*)p; break;
            case 64000000:  child_num = (const float*)p; break;
            case 25600000:  emb_root  = (const float*)p; break;
            case 51200000:  emb_child = (const float*)p; break;
            case 36864:     W = (const float*)p; break;
            case 32:        bias = (const float*)p; break;
            case 64:
                if (!gamma_r) gamma_r = (const float*)p; else beta_r = (const float*)p;
                break;
            case 128:
                if (!gamma_c) gamma_c = (const float*)p; else beta_c = (const float*)p;
                break;
            default: break;
        }
    }

    float* out = (float*)d_out;

    k_reset<<<1, 256>>>();
    k_stats_child<<<NCHILD / 128, 128>>>(cfi, child_num);
    k_stats_root<<<B_ROOT / 128, 64>>>(idx, root_num);
    k_finalize<<<1, 128>>>(gamma_c, beta_c, gamma_r, beta_r, W, bias);

    const int proj_smem = (PROJ_ROWS * EPITCH + DIM * OUTD) * (int)sizeof(float); // 74752 B
    cudaFuncSetAttribute(k_proj, cudaFuncAttributeMaxDynamicSharedMemorySize, proj_smem);
    dim3 pgrid(CC, (VOCAB + PROJ_ROWS - 1) / PROJ_ROWS);
    k_proj<<<pgrid, 256, proj_smem>>>(emb_child, W);

    k_root<<<B_ROOT / 8, 256>>>(idx, root_cat, root_num, emb_root, out);
    k_child<<<NCHILD / 256, 256>>>(cfi, child_cat, child_num, out);
}

// round 7
// speedup vs baseline: 2.5102x; 1.2325x over previous
#include <cuda_runtime.h>
#include <cuda_bf16.h>
#include <cstdint>

#define B_ROOT   8192
#define KFAN     16
#define NCHILD   (B_ROOT * KFAN)     // 131072
#define VOCAB    50000
#define DIM      64
#define CR       8
#define NR       64
#define CC       16
#define NC       128
#define OUTD     32
#define KDIM     (CC * DIM + NC)     // 1152
#define OUTCOLS  (CR * DIM + NR + OUTD)  // 608
#define EPSBN    1e-5f

#define PROJ_ROWS 256
#define EPITCH    (DIM + 1)                       // 65 -> conflict-free column reads
#define VTILES    ((VOCAB + PROJ_ROWS - 1) / PROJ_ROWS)   // 196
#define SC_BLKS   (NCHILD / 256)                  // 512 stats_child blocks
#define SR_BLKS   (B_ROOT / 128)                  // 64 stats_root blocks
#define BIG1_BLKS (SC_BLKS + SR_BLKS + CC * VTILES)   // 512+64+3136 = 3712
#define CH_BLKS   (NCHILD / 256)                  // 512
#define RT_BLKS   (B_ROOT / 8)                    // 1024
#define BIG2_BLKS (CH_BLKS + RT_BLKS)             // 1536

// ---------------- scratch (device globals; allocation-free) ----------------
__device__ __align__(16) double g_sum_c[NC];
__device__ __align__(16) double g_ss_c [NC];
__device__ __align__(16) double g_sum_r[NR];
__device__ __align__(16) double g_ss_r [NR];
__device__ __align__(16) float g_a_c[NC];
__device__ __align__(16) float g_s_c[NC];
__device__ __align__(16) float g_a_r[NR];
__device__ __align__(16) float g_s_r[NR];
__device__ __align__(16) float g_wn[NC * OUTD];   // BN-folded numeric weight [k][o]
__device__ __align__(16) float g_bp[OUTD];        // bias + shift @ Wn^T
// bf16-packed categorical projection: 16 bf16x2 words per (c,v) row = 64 B
__device__ __align__(256) unsigned g_projp[CC * VOCAB * (OUTD / 2)];   // 51.2 MB

// ---------------- packed f32x2 helpers ----------------
__device__ __forceinline__ unsigned long long pack2(float a, float b) {
    unsigned long long r;
    asm("mov.b64 %0, {%1, %2};" : "=l"(r) : "f"(a), "f"(b));
    return r;
}
__device__ __forceinline__ void unpack2(unsigned long long v, float& lo, float& hi) {
    asm("mov.b64 {%0, %1}, %2;" : "=f"(lo), "=f"(hi) : "l"(v));
}
__device__ __forceinline__ void fma2(unsigned long long& d, unsigned long long a, unsigned long long b) {
    asm("fma.rn.f32x2 %0, %1, %2, %0;" : "+l"(d) : "l"(a), "l"(b));
}

// ---------------- kernel 0: reset stat accumulators ----------------
__global__ void k_reset() {
    int t = threadIdx.x;
    if (t < NC) { g_sum_c[t] = 0.0; g_ss_c[t] = 0.0; }
    if (t < NR) { g_sum_r[t] = 0.0; g_ss_r[t] = 0.0; }
}

// ---------------- kernel 1: big1 = stats_child ∪ stats_root ∪ proj ----------------
__global__ __launch_bounds__(256)
void k_big1(const int* __restrict__ cfi, const float* __restrict__ child_num,
            const int* __restrict__ idx, const float* __restrict__ root_num,
            const float* __restrict__ emb_child, const float* __restrict__ W) {
    extern __shared__ float sm[];
    int bid = blockIdx.x;
    int t = threadIdx.x;

    if (bid < SC_BLKS) {
        // ---- child BN stats: 256 rows per block, col = t&127, 2 row-halves ----
        int* rid = (int*)sm;
        rid[t] = cfi[bid * 256 + t];
        __syncthreads();
        int col = t & 127;
        int r0 = (t >> 7) * 128;
        float s[8], ss[8];
#pragma unroll
        for (int u = 0; u < 8; ++u) { s[u] = 0.f; ss[u] = 0.f; }
        for (int r = r0; r < r0 + 128; r += 8) {
            float x[8];
#pragma unroll
            for (int u = 0; u < 8; ++u) {
                int g = rid[r + u];
                x[u] = __ldg(&child_num[(size_t)g * NC + col]);
            }
#pragma unroll
            for (int u = 0; u < 8; ++u) { s[u] += x[u]; ss[u] += x[u] * x[u]; }
        }
        float st  = (s[0]+s[1])+(s[2]+s[3])+((s[4]+s[5])+(s[6]+s[7]));
        float sst = (ss[0]+ss[1])+(ss[2]+ss[3])+((ss[4]+ss[5])+(ss[6]+ss[7]));
        atomicAdd(&g_sum_c[col], (double)st);
        atomicAdd(&g_ss_c[col],  (double)sst);
        return;
    }
    if (bid < SC_BLKS + SR_BLKS) {
        // ---- root BN stats: 128 rows per block, col = t&63, 4 row-quarters ----
        int b = bid - SC_BLKS;
        int* rid = (int*)sm;
        if (t < 128) rid[t] = idx[b * 128 + t];
        __syncthreads();
        int col = t & 63;
        int r0 = (t >> 6) * 32;
        float s[4], ss[4];
#pragma unroll
        for (int u = 0; u < 4; ++u) { s[u] = 0.f; ss[u] = 0.f; }
        for (int r = r0; r < r0 + 32; r += 4) {
            float x[4];
#pragma unroll
            for (int u = 0; u < 4; ++u) {
                int g = rid[r + u];
                x[u] = __ldg(&root_num[(size_t)g * NR + col]);
            }
#pragma unroll
            for (int u = 0; u < 4; ++u) { s[u] += x[u]; ss[u] += x[u] * x[u]; }
        }
        float st  = (s[0]+s[1])+(s[2]+s[3]);
        float sst = (ss[0]+ss[1])+(ss[2]+ss[3]);
        atomicAdd(&g_sum_r[col], (double)st);
        atomicAdd(&g_ss_r[col],  (double)sst);
        return;
    }

    // ---- proj: proj[c][v][:] = emb_child[c,v,:] @ W[:, c*64:+64]^T, bf16-packed ----
    int pb = bid - (SC_BLKS + SR_BLKS);
    int c  = pb / VTILES;
    int v0 = (pb % VTILES) * PROJ_ROWS;

    float* Er = sm;                          // [PROJ_ROWS][EPITCH]
    float* Ws = sm + PROJ_ROWS * EPITCH;     // [DIM][OUTD]

    for (int i = t; i < DIM * OUTD; i += 256) {
        int o = i >> 6, d = i & 63;
        Ws[d * OUTD + o] = W[(size_t)o * KDIM + c * DIM + d];
    }
    for (int i = t; i < PROJ_ROWS * DIM; i += 256) {
        int r = i >> 6, d = i & 63;
        int v = v0 + r;
        Er[r * EPITCH + d] = (v < VOCAB) ? emb_child[((size_t)c * VOCAB + v) * DIM + d] : 0.f;
    }
    __syncthreads();

    int v = v0 + t;
    unsigned long long acc[16];
#pragma unroll
    for (int j = 0; j < 16; ++j) acc[j] = pack2(0.f, 0.f);

    const float* er = Er + t * EPITCH;
#pragma unroll 8
    for (int d = 0; d < DIM; ++d) {
        float e = er[d];
        unsigned long long ee = pack2(e, e);
        const ulonglong2* wr = (const ulonglong2*)(Ws + d * OUTD);
#pragma unroll
        for (int p = 0; p < 8; ++p) {
            ulonglong2 w = wr[p];
            fma2(acc[2 * p],     ee, w.x);
            fma2(acc[2 * p + 1], ee, w.y);
        }
    }

    if (v < VOCAB) {
        unsigned us[16];
#pragma unroll
        for (int j = 0; j < 16; ++j) {
            float lo, hi;
            unpack2(acc[j], lo, hi);
            __nv_bfloat162 b2 = __float22bfloat162_rn(make_float2(lo, hi)); // .x = lo
            us[j] = *reinterpret_cast<unsigned*>(&b2);
        }
        uint4* outp = (uint4*)(g_projp + ((size_t)c * VOCAB + v) * 16);
        outp[0] = make_uint4(us[0],  us[1],  us[2],  us[3]);
        outp[1] = make_uint4(us[4],  us[5],  us[6],  us[7]);
        outp[2] = make_uint4(us[8],  us[9],  us[10], us[11]);
        outp[3] = make_uint4(us[12], us[13], us[14], us[15]);
    }
}

// ---------------- kernel 2: finalize BN + fold numeric weights ----------------
__global__ void k_finalize(const float* __restrict__ gamma_c, const float* __restrict__ beta_c,
                           const float* __restrict__ gamma_r, const float* __restrict__ beta_r,
                           const float* __restrict__ W, const float* __restrict__ bias) {
    int t = threadIdx.x;
    if (t < NC) {
        double m = g_sum_c[t] * (1.0 / (double)NCHILD);
        double v = g_ss_c[t] * (1.0 / (double)NCHILD) - m * m;
        float a = gamma_c[t] * rsqrtf((float)v + EPSBN);
        g_a_c[t] = a;
        g_s_c[t] = beta_c[t] - (float)m * a;
    }
    if (t < NR) {
        double m = g_sum_r[t] * (1.0 / (double)B_ROOT);
        double v = g_ss_r[t] * (1.0 / (double)B_ROOT) - m * m;
        float a = gamma_r[t] * rsqrtf((float)v + EPSBN);
        g_a_r[t] = a;
        g_s_r[t] = beta_r[t] - (float)m * a;
    }
    __syncthreads();
    for (int i = t; i < NC * OUTD; i += 128) {
        int k = i >> 5, o = i & 31;
        g_wn[i] = g_a_c[k] * W[(size_t)o * KDIM + CC * DIM + k];
    }
    {
        int o = t >> 2;          // 0..31
        int sl = t & 3;
        const float* wrow = W + (size_t)o * KDIM + CC * DIM;
        float a0 = 0.f, a1 = 0.f, a2 = 0.f, a3 = 0.f;
#pragma unroll
        for (int j = 0; j < 8; ++j) {
            a0 += g_s_c[sl + 16 * j +  0] * wrow[sl + 16 * j +  0];
            a1 += g_s_c[sl + 16 * j +  4] * wrow[sl + 16 * j +  4];
            a2 += g_s_c[sl + 16 * j +  8] * wrow[sl + 16 * j +  8];
            a3 += g_s_c[sl + 16 * j + 12] * wrow[sl + 16 * j + 12];
        }
        float acc = (a0 + a1) + (a2 + a3);
        acc += __shfl_xor_sync(0xffffffffu, acc, 1);
        acc += __shfl_xor_sync(0xffffffffu, acc, 2);
        if (sl == 0) g_bp[o] = acc + bias[o];
    }
}

// ---------------- kernel 3: big2 = child ∪ root ----------------
__global__ __launch_bounds__(256)
void k_big2(const int* __restrict__ cfi, const int* __restrict__ child_cat,
            const float* __restrict__ child_num,
            const int* __restrict__ idx, const int* __restrict__ root_cat,
            const float* __restrict__ root_num, const float* __restrict__ emb_root,
            float* __restrict__ out) {
    extern __shared__ float sm[];
    int bid = blockIdx.x;
    int t = threadIdx.x;
    int lane = t & 31;

    if (bid >= CH_BLKS) {
        // ---- root part: one warp per root row ----
        int warp = (bid - CH_BLKS) * 8 + (t >> 5);
        int g = idx[warp];
        const int* cr = root_cat + (size_t)g * CR;
        float* orow = out + (size_t)warp * OUTCOLS;
#pragma unroll
        for (int c = 0; c < CR; ++c) {
            int v = cr[c];
            const float2* e = (const float2*)(emb_root + ((size_t)c * VOCAB + v) * DIM);
            *(float2*)(orow + c * DIM + lane * 2) = e[lane];
        }
        float2 x  = *(const float2*)(root_num + (size_t)g * NR + lane * 2);
        float2 a  = ((const float2*)g_a_r)[lane];
        float2 sh = ((const float2*)g_s_r)[lane];
        float2 y;
        y.x = fmaf(x.x, a.x, sh.x);
        y.y = fmaf(x.y, a.y, sh.y);
        *(float2*)(orow + CR * DIM + lane * 2) = y;
        return;
    }

    // ---- child part ----
    float* Wn = sm;   // [NC][OUTD] = 16 KB
    for (int i = t; i < NC * OUTD; i += 256)
        Wn[i] = g_wn[i];
    __syncthreads();

    int row = bid * 256 + t;
    int g = cfi[row];

    // categorical: 16 bf16-packed proj rows, fp32 scalar accumulate
    float racc[32];
#pragma unroll
    for (int i = 0; i < 32; ++i) racc[i] = 0.f;

    int cats[CC];
    {
        const int4* crow4 = (const int4*)(child_cat + (size_t)g * CC);
#pragma unroll
        for (int q = 0; q < CC / 4; ++q) {
            int4 c4 = crow4[q];
            cats[4 * q + 0] = c4.x;
            cats[4 * q + 1] = c4.y;
            cats[4 * q + 2] = c4.z;
            cats[4 * q + 3] = c4.w;
        }
    }
#pragma unroll 4
    for (int c = 0; c < CC; ++c) {
        const uint4* p = (const uint4*)(g_projp + ((size_t)c * VOCAB + cats[c]) * 16);
        uint4 q0 = p[0], q1 = p[1], q2 = p[2], q3 = p[3];
        unsigned us[16] = {q0.x, q0.y, q0.z, q0.w, q1.x, q1.y, q1.z, q1.w,
                           q2.x, q2.y, q2.z, q2.w, q3.x, q3.y, q3.z, q3.w};
#pragma unroll
        for (int j = 0; j < 16; ++j) {
            __nv_bfloat162 b2 = *reinterpret_cast<__nv_bfloat162*>(&us[j]);
            float2 f = __bfloat1622float2(b2);   // .x = output 2j, .y = 2j+1
            racc[2 * j]     += f.x;
            racc[2 * j + 1] += f.y;
        }
    }

    // numeric: x @ (a ⊙ Wn)^T, packed f32x2, bias folded into g_bp
    unsigned long long acc[16];
#pragma unroll
    for (int p = 0; p < 16; ++p) {
        float2 bb = ((const float2*)g_bp)[p];
        acc[p] = pack2(bb.x, bb.y);
    }
    const float4* nrow = (const float4*)(child_num + (size_t)g * NC);
#pragma unroll 4
    for (int j = 0; j < NC / 4; ++j) {
        float4 x = nrow[j];
        const float h[4] = {x.x, x.y, x.z, x.w};
#pragma unroll
        for (int q = 0; q < 4; ++q) {
            unsigned long long hh = pack2(h[q], h[q]);
            const ulonglong2* wrow = (const ulonglong2*)(Wn + (j * 4 + q) * OUTD);
#pragma unroll
            for (int p = 0; p < 8; ++p) {
                ulonglong2 w = wrow[p];
                fma2(acc[2 * p],     hh, w.x);
                fma2(acc[2 * p + 1], hh, w.y);
            }
        }
    }

    // ReLU(cat + num), then mean over 16 consecutive rows via shfl (reuse racc)
#pragma unroll
    for (int p = 0; p < 16; ++p) {
        float lo, hi;
        unpack2(acc[p], lo, hi);
        racc[2 * p]     = fmaxf(racc[2 * p]     + lo, 0.f);
        racc[2 * p + 1] = fmaxf(racc[2 * p + 1] + hi, 0.f);
    }
#pragma unroll
    for (int s = 1; s < 16; s <<= 1) {
#pragma unroll
        for (int i = 0; i < 32; ++i)
            racc[i] += __shfl_xor_sync(0xffffffffu, racc[i], s);
    }
    int sub  = lane & 15;
    int root = row >> 4;
    float2 val;
    val.x = racc[2 * sub]     * (1.0f / (float)KFAN);
    val.y = racc[2 * sub + 1] * (1.0f / (float)KFAN);
    *(float2*)(out + (size_t)root * OUTCOLS + CR * DIM + NR + 2 * sub) = val;
}

// ---------------- launch ----------------
extern "C" void kernel_launch(void* const* d_in, const int* in_sizes, int n_in,
                              void* d_out, int out_size) {
    const int *idx = nullptr, *cfi = nullptr, *root_cat = nullptr, *child_cat = nullptr;
    const float *root_num = nullptr, *child_num = nullptr;
    const float *emb_root = nullptr, *emb_child = nullptr;
    const float *W = nullptr, *bias = nullptr;
    const float *gamma_r = nullptr, *beta_r = nullptr, *gamma_c = nullptr, *beta_c = nullptr;

    for (int i = 0; i < n_in; ++i) {
        long long s = in_sizes[i];
        void* p = d_in[i];
        switch (s) {
            case 8192:      idx = (const int*)p; break;
            case 131072:    cfi = (const int*)p; break;
            case 1600000:   root_cat  = (const int*)p; break;
            case 8000000:   child_cat = (const int*)p; break;
            case 12800000:  root_num  = (const float*)p; break;
            case 64000000:  child_num = (const float*)p; break;
            case 25600000:  emb_root  = (const float*)p; break;
            case 51200000:  emb_child = (const float*)p; break;
            case 36864:     W = (const float*)p; break;
            case 32:        bias = (const float*)p; break;
            case 64:
                if (!gamma_r) gamma_r = (const float*)p; else beta_r = (const float*)p;
                break;
            case 128:
                if (!gamma_c) gamma_c = (const float*)p; else beta_c = (const float*)p;
                break;
            default: break;
        }
    }

    float* out = (float*)d_out;

    const int big1_smem = (PROJ_ROWS * EPITCH + DIM * OUTD) * (int)sizeof(float); // 74752 B
    cudaFuncSetAttribute(k_big1, cudaFuncAttributeMaxDynamicSharedMemorySize, big1_smem);
    const int big2_smem = NC * OUTD * (int)sizeof(float);                         // 16384 B

    k_reset<<<1, 256>>>();
    k_big1<<<BIG1_BLKS, 256, big1_smem>>>(cfi, child_num, idx, root_num, emb_child, W);
    k_finalize<<<1, 128>>>(gamma_c, beta_c, gamma_r, beta_r, W, bias);
    k_big2<<<BIG2_BLKS, 256, big2_smem>>>(cfi, child_cat, child_num,
                                          idx, root_cat, root_num, emb_root, out);
}

// round 8
// speedup vs baseline: 2.5773x; 1.0267x over previous
#include <cuda_runtime.h>
#include <cuda_bf16.h>
#include <cstdint>

#define B_ROOT   8192
#define KFAN     16
#define NCHILD   (B_ROOT * KFAN)     // 131072
#define VOCAB    50000
#define DIM      64
#define CR       8
#define NR       64
#define CC       16
#define NC       128
#define OUTD     32
#define KDIM     (CC * DIM + NC)     // 1152
#define OUTCOLS  (CR * DIM + NR + OUTD)  // 608
#define EPSBN    1e-5f

#define PROJ_ROWS 256
#define EPITCH    (DIM + 1)                       // 65 -> conflict-free column reads
#define VTILES    ((VOCAB + PROJ_ROWS - 1) / PROJ_ROWS)   // 196
#define SC_BLKS   (NCHILD / 256)                  // 512 stats_child blocks
#define SR_BLKS   (B_ROOT / 128)                  // 64 stats_root blocks
#define BIG1_BLKS (SC_BLKS + SR_BLKS + CC * VTILES)   // 3712
#define CH_BLKS   (NCHILD / 256)                  // 512
#define RT_BLKS   (B_ROOT / 8)                    // 1024
#define BIG2_BLKS (CH_BLKS + RT_BLKS)             // 1536

// ---------------- scratch (device globals; allocation-free) ----------------
__device__ __align__(16) double g_sum_c[NC];
__device__ __align__(16) double g_ss_c [NC];
__device__ __align__(16) double g_sum_r[NR];
__device__ __align__(16) double g_ss_r [NR];
__device__ __align__(16) float g_a_c[NC];
__device__ __align__(16) float g_s_c[NC];
__device__ __align__(16) float g_a_r[NR];
__device__ __align__(16) float g_s_r[NR];
__device__ __align__(16) float g_wn[NC * OUTD];   // BN-folded numeric weight [k][o]
__device__ __align__(16) float g_bp[OUTD];        // bias + shift @ Wn^T
// bf16-packed categorical projection: 16 bf16x2 words per (c,v) row = 64 B
__device__ __align__(256) unsigned g_projp[CC * VOCAB * (OUTD / 2)];   // 51.2 MB

// ---------------- packed f32x2 helpers ----------------
__device__ __forceinline__ unsigned long long pack2(float a, float b) {
    unsigned long long r;
    asm("mov.b64 %0, {%1, %2};" : "=l"(r) : "f"(a), "f"(b));
    return r;
}
__device__ __forceinline__ void unpack2(unsigned long long v, float& lo, float& hi) {
    asm("mov.b64 {%0, %1}, %2;" : "=f"(lo), "=f"(hi) : "l"(v));
}
__device__ __forceinline__ void fma2(unsigned long long& d, unsigned long long a, unsigned long long b) {
    asm("fma.rn.f32x2 %0, %1, %2, %0;" : "+l"(d) : "l"(a), "l"(b));
}
__device__ __forceinline__ void add2(unsigned long long& d, unsigned long long a) {
    asm("add.rn.f32x2 %0, %0, %1;" : "+l"(d) : "l"(a));
}
// accumulate one bf16x2 word into an f32x2 acc
__device__ __forceinline__ void addbf2(unsigned long long& d, unsigned w) {
    __nv_bfloat162 b2 = *reinterpret_cast<__nv_bfloat162*>(&w);
    float2 f = __bfloat1622float2(b2);
    add2(d, pack2(f.x, f.y));
}

// ---------------- kernel 0: reset stat accumulators ----------------
__global__ void k_reset() {
    int t = threadIdx.x;
    if (t < NC) { g_sum_c[t] = 0.0; g_ss_c[t] = 0.0; }
    if (t < NR) { g_sum_r[t] = 0.0; g_ss_r[t] = 0.0; }
}

// ---------------- kernel 1: big1 = stats_child ∪ stats_root ∪ proj ----------------
__global__ __launch_bounds__(256)
void k_big1(const int* __restrict__ cfi, const float* __restrict__ child_num,
            const int* __restrict__ idx, const float* __restrict__ root_num,
            const float* __restrict__ emb_child, const float* __restrict__ W) {
    extern __shared__ float sm[];
    int bid = blockIdx.x;
    int t = threadIdx.x;

    if (bid < SC_BLKS) {
        // ---- child BN stats: 256 rows per block, col = t&127, 2 row-halves ----
        int* rid = (int*)sm;
        rid[t] = cfi[bid * 256 + t];
        __syncthreads();
        int col = t & 127;
        int r0 = (t >> 7) * 128;
        float s[8], ss[8];
#pragma unroll
        for (int u = 0; u < 8; ++u) { s[u] = 0.f; ss[u] = 0.f; }
        for (int r = r0; r < r0 + 128; r += 8) {
            float x[8];
#pragma unroll
            for (int u = 0; u < 8; ++u) {
                int g = rid[r + u];
                x[u] = __ldg(&child_num[(size_t)g * NC + col]);
            }
#pragma unroll
            for (int u = 0; u < 8; ++u) { s[u] += x[u]; ss[u] += x[u] * x[u]; }
        }
        float st  = (s[0]+s[1])+(s[2]+s[3])+((s[4]+s[5])+(s[6]+s[7]));
        float sst = (ss[0]+ss[1])+(ss[2]+ss[3])+((ss[4]+ss[5])+(ss[6]+ss[7]));
        atomicAdd(&g_sum_c[col], (double)st);
        atomicAdd(&g_ss_c[col],  (double)sst);
        return;
    }
    if (bid < SC_BLKS + SR_BLKS) {
        // ---- root BN stats: 128 rows per block, col = t&63, 4 row-quarters ----
        int b = bid - SC_BLKS;
        int* rid = (int*)sm;
        if (t < 128) rid[t] = idx[b * 128 + t];
        __syncthreads();
        int col = t & 63;
        int r0 = (t >> 6) * 32;
        float s[4], ss[4];
#pragma unroll
        for (int u = 0; u < 4; ++u) { s[u] = 0.f; ss[u] = 0.f; }
        for (int r = r0; r < r0 + 32; r += 4) {
            float x[4];
#pragma unroll
            for (int u = 0; u < 4; ++u) {
                int g = rid[r + u];
                x[u] = __ldg(&root_num[(size_t)g * NR + col]);
            }
#pragma unroll
            for (int u = 0; u < 4; ++u) { s[u] += x[u]; ss[u] += x[u] * x[u]; }
        }
        float st  = (s[0]+s[1])+(s[2]+s[3]);
        float sst = (ss[0]+ss[1])+(ss[2]+ss[3]);
        atomicAdd(&g_sum_r[col], (double)st);
        atomicAdd(&g_ss_r[col],  (double)sst);
        return;
    }

    // ---- proj: proj[c][v][:] = emb_child[c,v,:] @ W[:, c*64:+64]^T, bf16-packed ----
    int pb = bid - (SC_BLKS + SR_BLKS);
    int c  = pb / VTILES;
    int v0 = (pb % VTILES) * PROJ_ROWS;

    float* Er = sm;                          // [PROJ_ROWS][EPITCH]
    float* Ws = sm + PROJ_ROWS * EPITCH;     // [DIM][OUTD]

    for (int i = t; i < DIM * OUTD; i += 256) {
        int o = i >> 6, d = i & 63;
        Ws[d * OUTD + o] = W[(size_t)o * KDIM + c * DIM + d];
    }
    for (int i = t; i < PROJ_ROWS * DIM; i += 256) {
        int r = i >> 6, d = i & 63;
        int v = v0 + r;
        Er[r * EPITCH + d] = (v < VOCAB) ? emb_child[((size_t)c * VOCAB + v) * DIM + d] : 0.f;
    }
    __syncthreads();

    int v = v0 + t;
    unsigned long long acc[16];
#pragma unroll
    for (int j = 0; j < 16; ++j) acc[j] = pack2(0.f, 0.f);

    const float* er = Er + t * EPITCH;
#pragma unroll 8
    for (int d = 0; d < DIM; ++d) {
        float e = er[d];
        unsigned long long ee = pack2(e, e);
        const ulonglong2* wr = (const ulonglong2*)(Ws + d * OUTD);
#pragma unroll
        for (int p = 0; p < 8; ++p) {
            ulonglong2 w = wr[p];
            fma2(acc[2 * p],     ee, w.x);
            fma2(acc[2 * p + 1], ee, w.y);
        }
    }

    if (v < VOCAB) {
        unsigned us[16];
#pragma unroll
        for (int j = 0; j < 16; ++j) {
            float lo, hi;
            unpack2(acc[j], lo, hi);
            __nv_bfloat162 b2 = __float22bfloat162_rn(make_float2(lo, hi)); // .x = lo
            us[j] = *reinterpret_cast<unsigned*>(&b2);
        }
        uint4* outp = (uint4*)(g_projp + ((size_t)c * VOCAB + v) * 16);
        outp[0] = make_uint4(us[0],  us[1],  us[2],  us[3]);
        outp[1] = make_uint4(us[4],  us[5],  us[6],  us[7]);
        outp[2] = make_uint4(us[8],  us[9],  us[10], us[11]);
        outp[3] = make_uint4(us[12], us[13], us[14], us[15]);
    }
}

// ---------------- kernel 2: finalize BN + fold numeric weights (wide) ----------------
__global__ __launch_bounds__(1024)
void k_finalize(const float* __restrict__ gamma_c, const float* __restrict__ beta_c,
                const float* __restrict__ gamma_r, const float* __restrict__ beta_r,
                const float* __restrict__ W, const float* __restrict__ bias) {
    int t = threadIdx.x;
    if (t < NC) {
        double m = g_sum_c[t] * (1.0 / (double)NCHILD);
        double v = g_ss_c[t] * (1.0 / (double)NCHILD) - m * m;
        float a = gamma_c[t] * rsqrtf((float)v + EPSBN);
        g_a_c[t] = a;
        g_s_c[t] = beta_c[t] - (float)m * a;
    }
    if (t < NR) {
        double m = g_sum_r[t] * (1.0 / (double)B_ROOT);
        double v = g_ss_r[t] * (1.0 / (double)B_ROOT) - m * m;
        float a = gamma_r[t] * rsqrtf((float)v + EPSBN);
        g_a_r[t] = a;
        g_s_r[t] = beta_r[t] - (float)m * a;
    }
    __syncthreads();
    // fold: g_wn[k][o] = a_c[k] * W[o][CC*DIM + k]   (4096 elems, 1024 threads)
    for (int i = t; i < NC * OUTD; i += 1024) {
        int k = i >> 5, o = i & 31;
        g_wn[i] = g_a_c[k] * W[(size_t)o * KDIM + CC * DIM + k];
    }
    // g_bp[o] = bias[o] + sum_k s_c[k] * W[o][CC*DIM + k]  (first 128 threads; 4/o)
    if (t < 128) {
        int o = t >> 2;          // 0..31
        int sl = t & 3;
        const float* wrow = W + (size_t)o * KDIM + CC * DIM;
        float a0 = 0.f, a1 = 0.f, a2 = 0.f, a3 = 0.f;
#pragma unroll
        for (int j = 0; j < 8; ++j) {
            a0 += g_s_c[sl + 16 * j +  0] * wrow[sl + 16 * j +  0];
            a1 += g_s_c[sl + 16 * j +  4] * wrow[sl + 16 * j +  4];
            a2 += g_s_c[sl + 16 * j +  8] * wrow[sl + 16 * j +  8];
            a3 += g_s_c[sl + 16 * j + 12] * wrow[sl + 16 * j + 12];
        }
        float acc = (a0 + a1) + (a2 + a3);
        acc += __shfl_xor_sync(0xffffffffu, acc, 1);
        acc += __shfl_xor_sync(0xffffffffu, acc, 2);
        if (sl == 0) g_bp[o] = acc + bias[o];
    }
}

// ---------------- kernel 3: big2 = child ∪ root ----------------
__global__ __launch_bounds__(256, 3)
void k_big2(const int* __restrict__ cfi, const int* __restrict__ child_cat,
            const float* __restrict__ child_num,
            const int* __restrict__ idx, const int* __restrict__ root_cat,
            const float* __restrict__ root_num, const float* __restrict__ emb_root,
            float* __restrict__ out) {
    extern __shared__ float sm[];
    int bid = blockIdx.x;
    int t = threadIdx.x;
    int lane = t & 31;

    if (bid >= CH_BLKS) {
        // ---- root part: one warp per root row ----
        int warp = (bid - CH_BLKS) * 8 + (t >> 5);
        int g = idx[warp];
        const int* cr = root_cat + (size_t)g * CR;
        float* orow = out + (size_t)warp * OUTCOLS;
#pragma unroll
        for (int c = 0; c < CR; ++c) {
            int v = cr[c];
            const float2* e = (const float2*)(emb_root + ((size_t)c * VOCAB + v) * DIM);
            *(float2*)(orow + c * DIM + lane * 2) = e[lane];
        }
        float2 x  = *(const float2*)(root_num + (size_t)g * NR + lane * 2);
        float2 a  = ((const float2*)g_a_r)[lane];
        float2 sh = ((const float2*)g_s_r)[lane];
        float2 y;
        y.x = fmaf(x.x, a.x, sh.x);
        y.y = fmaf(x.y, a.y, sh.y);
        *(float2*)(orow + CR * DIM + lane * 2) = y;
        return;
    }

    // ---- child part ----
    float* Wn = sm;   // [NC][OUTD] = 16 KB
    for (int i = t; i < NC * OUTD; i += 256)
        Wn[i] = g_wn[i];
    __syncthreads();

    int row = bid * 256 + t;
    int g = cfi[row];

    // single f32x2 accumulator set, init with folded bias
    unsigned long long acc[16];
#pragma unroll
    for (int p = 0; p < 16; ++p) {
        float2 bb = ((const float2*)g_bp)[p];
        acc[p] = pack2(bb.x, bb.y);
    }

    int cats[CC];
    {
        const int4* crow4 = (const int4*)(child_cat + (size_t)g * CC);
#pragma unroll
        for (int q = 0; q < CC / 4; ++q) {
            int4 c4 = crow4[q];
            cats[4 * q + 0] = c4.x;
            cats[4 * q + 1] = c4.y;
            cats[4 * q + 2] = c4.z;
            cats[4 * q + 3] = c4.w;
        }
    }

    // categorical: 16 bf16-packed proj gathers, 1-row lookahead pipeline
    {
        const uint4* pp = (const uint4*)(g_projp + ((size_t)0 * VOCAB + cats[0]) * 16);
        uint4 q0 = pp[0], q1 = pp[1], q2 = pp[2], q3 = pp[3];
#pragma unroll
        for (int c = 0; c < CC; ++c) {
            uint4 n0, n1, n2, n3;
            if (c + 1 < CC) {
                const uint4* pn = (const uint4*)(g_projp + ((size_t)(c + 1) * VOCAB + cats[c + 1]) * 16);
                n0 = pn[0]; n1 = pn[1]; n2 = pn[2]; n3 = pn[3];
            }
            addbf2(acc[0],  q0.x); addbf2(acc[1],  q0.y);
            addbf2(acc[2],  q0.z); addbf2(acc[3],  q0.w);
            addbf2(acc[4],  q1.x); addbf2(acc[5],  q1.y);
            addbf2(acc[6],  q1.z); addbf2(acc[7],  q1.w);
            addbf2(acc[8],  q2.x); addbf2(acc[9],  q2.y);
            addbf2(acc[10], q2.z); addbf2(acc[11], q2.w);
            addbf2(acc[12], q3.x); addbf2(acc[13], q3.y);
            addbf2(acc[14], q3.z); addbf2(acc[15], q3.w);
            q0 = n0; q1 = n1; q2 = n2; q3 = n3;
        }
    }

    // numeric: x @ (a ⊙ Wn)^T, packed f32x2
    const float4* nrow = (const float4*)(child_num + (size_t)g * NC);
#pragma unroll 4
    for (int j = 0; j < NC / 4; ++j) {
        float4 x = nrow[j];
        const float h[4] = {x.x, x.y, x.z, x.w};
#pragma unroll
        for (int q = 0; q < 4; ++q) {
            unsigned long long hh = pack2(h[q], h[q]);
            const ulonglong2* wrow = (const ulonglong2*)(Wn + (j * 4 + q) * OUTD);
#pragma unroll
            for (int p = 0; p < 8; ++p) {
                ulonglong2 w = wrow[p];
                fma2(acc[2 * p],     hh, w.x);
                fma2(acc[2 * p + 1], hh, w.y);
            }
        }
    }

    // ReLU, then mean over 16 consecutive rows (one root) via shfl
    float r[32];
#pragma unroll
    for (int p = 0; p < 16; ++p) {
        float lo, hi;
        unpack2(acc[p], lo, hi);
        r[2 * p]     = fmaxf(lo, 0.f);
        r[2 * p + 1] = fmaxf(hi, 0.f);
    }
#pragma unroll
    for (int s = 1; s < 16; s <<= 1) {
#pragma unroll
        for (int i = 0; i < 32; ++i)
            r[i] += __shfl_xor_sync(0xffffffffu, r[i], s);
    }
    int sub  = lane & 15;
    int root = row >> 4;
    float2 val;
    val.x = r[2 * sub]     * (1.0f / (float)KFAN);
    val.y = r[2 * sub + 1] * (1.0f / (float)KFAN);
    *(float2*)(out + (size_t)root * OUTCOLS + CR * DIM + NR + 2 * sub) = val;
}

// ---------------- launch ----------------
extern "C" void kernel_launch(void* const* d_in, const int* in_sizes, int n_in,
                              void* d_out, int out_size) {
    const int *idx = nullptr, *cfi = nullptr, *root_cat = nullptr, *child_cat = nullptr;
    const float *root_num = nullptr, *child_num = nullptr;
    const float *emb_root = nullptr, *emb_child = nullptr;
    const float *W = nullptr, *bias = nullptr;
    const float *gamma_r = nullptr, *beta_r = nullptr, *gamma_c = nullptr, *beta_c = nullptr;

    for (int i = 0; i < n_in; ++i) {
        long long s = in_sizes[i];
        void* p = d_in[i];
        switch (s) {
            case 8192:      idx = (const int*)p; break;
            case 131072:    cfi = (const int*)p; break;
            case 1600000:   root_cat  = (const int*)p; break;
            case 8000000:   child_cat = (const int*)p; break;
            case 12800000:  root_num  = (const float*)p; break;
            case 64000000:  child_num = (const float*)p; break;
            case 25600000:  emb_root  = (const float*)p; break;
            case 51200000:  emb_child = (const float*)p; break;
            case 36864:     W = (const float*)p; break;
            case 32:        bias = (const float*)p; break;
            case 64:
                if (!gamma_r) gamma_r = (const float*)p; else beta_r = (const float*)p;
                break;
            case 128:
                if (!gamma_c) gamma_c = (const float*)p; else beta_c = (const float*)p;
                break;
            default: break;
        }
    }

    float* out = (float*)d_out;

    const int big1_smem = (PROJ_ROWS * EPITCH + DIM * OUTD) * (int)sizeof(float); // 74752 B
    cudaFuncSetAttribute(k_big1, cudaFuncAttributeMaxDynamicSharedMemorySize, big1_smem);
    const int big2_smem = NC * OUTD * (int)sizeof(float);                         // 16384 B

    k_reset<<<1, 256>>>();
    k_big1<<<BIG1_BLKS, 256, big1_smem>>>(cfi, child_num, idx, root_num, emb_child, W);
    k_finalize<<<1, 1024>>>(gamma_c, beta_c, gamma_r, beta_r, W, bias);
    k_big2<<<BIG2_BLKS, 256, big2_smem>>>(cfi, child_cat, child_num,
                                          idx, root_cat, root_num, emb_root, out);
}

// round 9
// speedup vs baseline: 3.2149x; 1.2474x over previous
#include <cuda_runtime.h>
#include <cuda_bf16.h>
#include <cstdint>

#define B_ROOT   8192
#define KFAN     16
#define NCHILD   (B_ROOT * KFAN)     // 131072
#define VOCAB    50000
#define DIM      64
#define CR       8
#define NR       64
#define CC       16
#define NC       128
#define OUTD     32
#define KDIM     (CC * DIM + NC)     // 1152
#define OUTCOLS  (CR * DIM + NR + OUTD)  // 608
#define EPSBN    1e-5f

#define PROJ_SPAN 512                               // rows per proj block (2 per thread)
#define VTILES    ((VOCAB + PROJ_SPAN - 1) / PROJ_SPAN)   // 98
#define SC_BLKS   (NCHILD / 256)                    // 512 stats_child blocks
#define SR_BLKS   (B_ROOT / 128)                    // 64 stats_root blocks
#define BIG1_BLKS (SC_BLKS + SR_BLKS + CC * VTILES) // 512+64+1568 = 2144
#define CH_BLKS   (NCHILD / 128)                    // 1024 (2 threads per child row)
#define RT_BLKS   (B_ROOT / 8)                      // 1024
#define BIG2_BLKS (CH_BLKS + RT_BLKS)               // 2048

// ---------------- scratch (device globals; allocation-free) ----------------
__device__ __align__(16) double g_sum_c[NC];
__device__ __align__(16) double g_ss_c [NC];
__device__ __align__(16) double g_sum_r[NR];
__device__ __align__(16) double g_ss_r [NR];
__device__ __align__(16) float g_a_c[NC];
__device__ __align__(16) float g_s_c[NC];
__device__ __align__(16) float g_a_r[NR];
__device__ __align__(16) float g_s_r[NR];
__device__ __align__(16) float g_wn[NC * OUTD];   // BN-folded numeric weight [k][o]
__device__ __align__(16) float g_bp[OUTD];        // bias + shift @ Wn^T
// bf16-packed categorical projection: 16 bf16x2 words per (c,v) row = 64 B
__device__ __align__(256) unsigned g_projp[CC * VOCAB * (OUTD / 2)];   // 51.2 MB

// ---------------- packed f32x2 helpers ----------------
__device__ __forceinline__ unsigned long long pack2(float a, float b) {
    unsigned long long r;
    asm("mov.b64 %0, {%1, %2};" : "=l"(r) : "f"(a), "f"(b));
    return r;
}
__device__ __forceinline__ void unpack2(unsigned long long v, float& lo, float& hi) {
    asm("mov.b64 {%0, %1}, %2;" : "=f"(lo), "=f"(hi) : "l"(v));
}
__device__ __forceinline__ void fma2(unsigned long long& d, unsigned long long a, unsigned long long b) {
    asm("fma.rn.f32x2 %0, %1, %2, %0;" : "+l"(d) : "l"(a), "l"(b));
}
__device__ __forceinline__ void add2(unsigned long long& d, unsigned long long a) {
    asm("add.rn.f32x2 %0, %0, %1;" : "+l"(d) : "l"(a));
}
__device__ __forceinline__ void addbf2(unsigned long long& d, unsigned w) {
    __nv_bfloat162 b2 = *reinterpret_cast<__nv_bfloat162*>(&w);
    float2 f = __bfloat1622float2(b2);
    add2(d, pack2(f.x, f.y));
}

// ---------------- kernel 0: reset stat accumulators ----------------
__global__ void k_reset() {
    int t = threadIdx.x;
    if (t < NC) { g_sum_c[t] = 0.0; g_ss_c[t] = 0.0; }
    if (t < NR) { g_sum_r[t] = 0.0; g_ss_r[t] = 0.0; }
}

// ---------------- kernel 1: big1 = stats_child ∪ stats_root ∪ proj ----------------
__global__ __launch_bounds__(256, 2)
void k_big1(const int* __restrict__ cfi, const float* __restrict__ child_num,
            const int* __restrict__ idx, const float* __restrict__ root_num,
            const float* __restrict__ emb_child, const float* __restrict__ W) {
    extern __shared__ float sm[];
    int bid = blockIdx.x;
    int t = threadIdx.x;

    if (bid < SC_BLKS) {
        // ---- child BN stats: 256 rows per block, col = t&127, 2 row-halves ----
        int* rid = (int*)sm;
        rid[t] = cfi[bid * 256 + t];
        __syncthreads();
        int col = t & 127;
        int r0 = (t >> 7) * 128;
        float s[8], ss[8];
#pragma unroll
        for (int u = 0; u < 8; ++u) { s[u] = 0.f; ss[u] = 0.f; }
        for (int r = r0; r < r0 + 128; r += 8) {
            float x[8];
#pragma unroll
            for (int u = 0; u < 8; ++u) {
                int g = rid[r + u];
                x[u] = __ldg(&child_num[(size_t)g * NC + col]);
            }
#pragma unroll
            for (int u = 0; u < 8; ++u) { s[u] += x[u]; ss[u] += x[u] * x[u]; }
        }
        float st  = (s[0]+s[1])+(s[2]+s[3])+((s[4]+s[5])+(s[6]+s[7]));
        float sst = (ss[0]+ss[1])+(ss[2]+ss[3])+((ss[4]+ss[5])+(ss[6]+ss[7]));
        atomicAdd(&g_sum_c[col], (double)st);
        atomicAdd(&g_ss_c[col],  (double)sst);
        return;
    }
    if (bid < SC_BLKS + SR_BLKS) {
        // ---- root BN stats: 128 rows per block, col = t&63, 4 row-quarters ----
        int b = bid - SC_BLKS;
        int* rid = (int*)sm;
        if (t < 128) rid[t] = idx[b * 128 + t];
        __syncthreads();
        int col = t & 63;
        int r0 = (t >> 6) * 32;
        float s[4], ss[4];
#pragma unroll
        for (int u = 0; u < 4; ++u) { s[u] = 0.f; ss[u] = 0.f; }
        for (int r = r0; r < r0 + 32; r += 4) {
            float x[4];
#pragma unroll
            for (int u = 0; u < 4; ++u) {
                int g = rid[r + u];
                x[u] = __ldg(&root_num[(size_t)g * NR + col]);
            }
#pragma unroll
            for (int u = 0; u < 4; ++u) { s[u] += x[u]; ss[u] += x[u] * x[u]; }
        }
        float st  = (s[0]+s[1])+(s[2]+s[3]);
        float sst = (ss[0]+ss[1])+(ss[2]+ss[3]);
        atomicAdd(&g_sum_r[col], (double)st);
        atomicAdd(&g_ss_r[col],  (double)sst);
        return;
    }

    // ---- proj: 2 vocab rows per thread; emb streamed via registers; W in smem ----
    int pb = bid - (SC_BLKS + SR_BLKS);
    int c  = pb / VTILES;
    int v0 = (pb % VTILES) * PROJ_SPAN;

    float* Ws = sm;                          // [DIM][OUTD] = 8 KB
    for (int i = t; i < DIM * OUTD; i += 256) {
        int o = i >> 6, d = i & 63;
        Ws[d * OUTD + o] = W[(size_t)o * KDIM + c * DIM + d];
    }
    __syncthreads();

    int va = v0 + t;
    int vb = va + 256;
    bool ga = va < VOCAB, gb = vb < VOCAB;
    const float4* ea4 = (const float4*)(emb_child + ((size_t)c * VOCAB + va) * DIM);
    const float4* eb4 = (const float4*)(emb_child + ((size_t)c * VOCAB + vb) * DIM);
    const float4 z4 = make_float4(0.f, 0.f, 0.f, 0.f);

    unsigned long long acc0[16], acc1[16];
#pragma unroll
    for (int j = 0; j < 16; ++j) { acc0[j] = pack2(0.f, 0.f); acc1[j] = pack2(0.f, 0.f); }

    float4 e0 = ga ? ea4[0] : z4;
    float4 e1 = gb ? eb4[0] : z4;
#pragma unroll 1
    for (int jb = 0; jb < 16; ++jb) {
        float4 n0 = z4, n1 = z4;
        if (jb < 15) {
            if (ga) n0 = ea4[jb + 1];
            if (gb) n1 = eb4[jb + 1];
        }
        const float ev0[4] = {e0.x, e0.y, e0.z, e0.w};
        const float ev1[4] = {e1.x, e1.y, e1.z, e1.w};
#pragma unroll
        for (int q = 0; q < 4; ++q) {
            int d = 4 * jb + q;
            unsigned long long h0 = pack2(ev0[q], ev0[q]);
            unsigned long long h1 = pack2(ev1[q], ev1[q]);
            const ulonglong2* wr = (const ulonglong2*)(Ws + d * OUTD);
#pragma unroll
            for (int p = 0; p < 8; ++p) {
                ulonglong2 w = wr[p];          // broadcast, serves both rows
                fma2(acc0[2 * p],     h0, w.x);
                fma2(acc0[2 * p + 1], h0, w.y);
                fma2(acc1[2 * p],     h1, w.x);
                fma2(acc1[2 * p + 1], h1, w.y);
            }
        }
        e0 = n0; e1 = n1;
    }

    if (ga) {
        unsigned us[16];
#pragma unroll
        for (int j = 0; j < 16; ++j) {
            float lo, hi; unpack2(acc0[j], lo, hi);
            __nv_bfloat162 b2 = __float22bfloat162_rn(make_float2(lo, hi));
            us[j] = *reinterpret_cast<unsigned*>(&b2);
        }
        uint4* outp = (uint4*)(g_projp + ((size_t)c * VOCAB + va) * 16);
        outp[0] = make_uint4(us[0],  us[1],  us[2],  us[3]);
        outp[1] = make_uint4(us[4],  us[5],  us[6],  us[7]);
        outp[2] = make_uint4(us[8],  us[9],  us[10], us[11]);
        outp[3] = make_uint4(us[12], us[13], us[14], us[15]);
    }
    if (gb) {
        unsigned us[16];
#pragma unroll
        for (int j = 0; j < 16; ++j) {
            float lo, hi; unpack2(acc1[j], lo, hi);
            __nv_bfloat162 b2 = __float22bfloat162_rn(make_float2(lo, hi));
            us[j] = *reinterpret_cast<unsigned*>(&b2);
        }
        uint4* outp = (uint4*)(g_projp + ((size_t)c * VOCAB + vb) * 16);
        outp[0] = make_uint4(us[0],  us[1],  us[2],  us[3]);
        outp[1] = make_uint4(us[4],  us[5],  us[6],  us[7]);
        outp[2] = make_uint4(us[8],  us[9],  us[10], us[11]);
        outp[3] = make_uint4(us[12], us[13], us[14], us[15]);
    }
}

// ---------------- kernel 2: finalize BN + fold numeric weights (wide) ----------------
__global__ __launch_bounds__(1024)
void k_finalize(const float* __restrict__ gamma_c, const float* __restrict__ beta_c,
                const float* __restrict__ gamma_r, const float* __restrict__ beta_r,
                const float* __restrict__ W, const float* __restrict__ bias) {
    int t = threadIdx.x;
    if (t < NC) {
        double m = g_sum_c[t] * (1.0 / (double)NCHILD);
        double v = g_ss_c[t] * (1.0 / (double)NCHILD) - m * m;
        float a = gamma_c[t] * rsqrtf((float)v + EPSBN);
        g_a_c[t] = a;
        g_s_c[t] = beta_c[t] - (float)m * a;
    }
    if (t < NR) {
        double m = g_sum_r[t] * (1.0 / (double)B_ROOT);
        double v = g_ss_r[t] * (1.0 / (double)B_ROOT) - m * m;
        float a = gamma_r[t] * rsqrtf((float)v + EPSBN);
        g_a_r[t] = a;
        g_s_r[t] = beta_r[t] - (float)m * a;
    }
    __syncthreads();
    for (int i = t; i < NC * OUTD; i += 1024) {
        int k = i >> 5, o = i & 31;
        g_wn[i] = g_a_c[k] * W[(size_t)o * KDIM + CC * DIM + k];
    }
    if (t < 128) {
        int o = t >> 2;
        int sl = t & 3;
        const float* wrow = W + (size_t)o * KDIM + CC * DIM;
        float a0 = 0.f, a1 = 0.f, a2 = 0.f, a3 = 0.f;
#pragma unroll
        for (int j = 0; j < 8; ++j) {
            a0 += g_s_c[sl + 16 * j +  0] * wrow[sl + 16 * j +  0];
            a1 += g_s_c[sl + 16 * j +  4] * wrow[sl + 16 * j +  4];
            a2 += g_s_c[sl + 16 * j +  8] * wrow[sl + 16 * j +  8];
            a3 += g_s_c[sl + 16 * j + 12] * wrow[sl + 16 * j + 12];
        }
        float acc = (a0 + a1) + (a2 + a3);
        acc += __shfl_xor_sync(0xffffffffu, acc, 1);
        acc += __shfl_xor_sync(0xffffffffu, acc, 2);
        if (sl == 0) g_bp[o] = acc + bias[o];
    }
}

// ---------------- kernel 3: big2 = child (2 threads/row) ∪ root ----------------
__global__ __launch_bounds__(256, 2)
void k_big2(const int* __restrict__ cfi, const int* __restrict__ child_cat,
            const float* __restrict__ child_num,
            const int* __restrict__ idx, const int* __restrict__ root_cat,
            const float* __restrict__ root_num, const float* __restrict__ emb_root,
            float* __restrict__ out) {
    extern __shared__ float sm[];
    int bid = blockIdx.x;
    int t = threadIdx.x;
    int lane = t & 31;

    if (bid >= CH_BLKS) {
        // ---- root part: one warp per root row ----
        int warp = (bid - CH_BLKS) * 8 + (t >> 5);
        int g = idx[warp];
        const int* cr = root_cat + (size_t)g * CR;
        float* orow = out + (size_t)warp * OUTCOLS;
#pragma unroll
        for (int c = 0; c < CR; ++c) {
            int v = cr[c];
            const float2* e = (const float2*)(emb_root + ((size_t)c * VOCAB + v) * DIM);
            *(float2*)(orow + c * DIM + lane * 2) = e[lane];
        }
        float2 x  = *(const float2*)(root_num + (size_t)g * NR + lane * 2);
        float2 a  = ((const float2*)g_a_r)[lane];
        float2 sh = ((const float2*)g_s_r)[lane];
        float2 y;
        y.x = fmaf(x.x, a.x, sh.x);
        y.y = fmaf(x.y, a.y, sh.y);
        *(float2*)(orow + CR * DIM + lane * 2) = y;
        return;
    }

    // ---- child part: warp = 16 rows (one root) x 2 half-threads ----
    float* Wn = sm;   // [NC][OUTD] = 16 KB
    for (int i = t; i < NC * OUTD; i += 256)
        Wn[i] = g_wn[i];
    __syncthreads();

    int warp  = t >> 5;
    int sub   = lane & 15;          // row within root
    int half  = lane >> 4;          // 0: cats 0-7 / k 0-63; 1: cats 8-15 / k 64-127
    int root  = bid * 8 + warp;
    int row   = root * KFAN + sub;
    int g     = cfi[row];

    unsigned long long acc[16];
#pragma unroll
    for (int p = 0; p < 16; ++p) {
        if (half == 0) {
            float2 bb = ((const float2*)g_bp)[p];
            acc[p] = pack2(bb.x, bb.y);
        } else {
            acc[p] = pack2(0.f, 0.f);
        }
    }

    // 8 categorical columns for this half
    int cats[8];
    {
        const int4* crow4 = (const int4*)(child_cat + (size_t)g * CC) + half * 2;
        int4 c0 = crow4[0], c1 = crow4[1];
        cats[0] = c0.x; cats[1] = c0.y; cats[2] = c0.z; cats[3] = c0.w;
        cats[4] = c1.x; cats[5] = c1.y; cats[6] = c1.z; cats[7] = c1.w;
    }
    int cbase = half * 8;

    // cat gathers with 1-row lookahead (4 uint4 in flight + next 4)
    {
        const uint4* pp = (const uint4*)(g_projp + ((size_t)cbase * VOCAB + cats[0]) * 16);
        uint4 q0 = pp[0], q1 = pp[1], q2 = pp[2], q3 = pp[3];
#pragma unroll
        for (int c = 0; c < 8; ++c) {
            uint4 n0, n1, n2, n3;
            if (c + 1 < 8) {
                const uint4* pn = (const uint4*)(g_projp + ((size_t)(cbase + c + 1) * VOCAB + cats[c + 1]) * 16);
                n0 = pn[0]; n1 = pn[1]; n2 = pn[2]; n3 = pn[3];
            }
            addbf2(acc[0],  q0.x); addbf2(acc[1],  q0.y);
            addbf2(acc[2],  q0.z); addbf2(acc[3],  q0.w);
            addbf2(acc[4],  q1.x); addbf2(acc[5],  q1.y);
            addbf2(acc[6],  q1.z); addbf2(acc[7],  q1.w);
            addbf2(acc[8],  q2.x); addbf2(acc[9],  q2.y);
            addbf2(acc[10], q2.z); addbf2(acc[11], q2.w);
            addbf2(acc[12], q3.x); addbf2(acc[13], q3.y);
            addbf2(acc[14], q3.z); addbf2(acc[15], q3.w);
            q0 = n0; q1 = n1; q2 = n2; q3 = n3;
        }
    }

    // numeric: 64 k-values for this half
    {
        const float4* nrow = (const float4*)(child_num + (size_t)g * NC + half * 64);
#pragma unroll 4
        for (int j = 0; j < 16; ++j) {
            float4 x = nrow[j];
            const float h[4] = {x.x, x.y, x.z, x.w};
            int kb = half * 64 + j * 4;
#pragma unroll
            for (int q = 0; q < 4; ++q) {
                unsigned long long hh = pack2(h[q], h[q]);
                const ulonglong2* wrow = (const ulonglong2*)(Wn + (kb + q) * OUTD);
#pragma unroll
                for (int p = 0; p < 8; ++p) {
                    ulonglong2 w = wrow[p];
                    fma2(acc[2 * p],     hh, w.x);
                    fma2(acc[2 * p + 1], hh, w.y);
                }
            }
        }
    }

    // combine halves (xor 16), ReLU, then 16-row mean (xor 1,2,4,8)
    float r[32];
#pragma unroll
    for (int p = 0; p < 16; ++p) {
        float lo, hi;
        unpack2(acc[p], lo, hi);
        r[2 * p] = lo; r[2 * p + 1] = hi;
    }
#pragma unroll
    for (int i = 0; i < 32; ++i) {
        r[i] += __shfl_xor_sync(0xffffffffu, r[i], 16);   // full row value
        r[i] = fmaxf(r[i], 0.f);                          // ReLU
    }
#pragma unroll
    for (int s = 1; s < 16; s <<= 1) {
#pragma unroll
        for (int i = 0; i < 32; ++i)
            r[i] += __shfl_xor_sync(0xffffffffu, r[i], s);
    }
    if (half == 0) {
        float2 val;
        val.x = r[2 * sub]     * (1.0f / (float)KFAN);
        val.y = r[2 * sub + 1] * (1.0f / (float)KFAN);
        *(float2*)(out + (size_t)root * OUTCOLS + CR * DIM + NR + 2 * sub) = val;
    }
}

// ---------------- launch ----------------
extern "C" void kernel_launch(void* const* d_in, const int* in_sizes, int n_in,
                              void* d_out, int out_size) {
    const int *idx = nullptr, *cfi = nullptr, *root_cat = nullptr, *child_cat = nullptr;
    const float *root_num = nullptr, *child_num = nullptr;
    const float *emb_root = nullptr, *emb_child = nullptr;
    const float *W = nullptr, *bias = nullptr;
    const float *gamma_r = nullptr, *beta_r = nullptr, *gamma_c = nullptr, *beta_c = nullptr;

    for (int i = 0; i < n_in; ++i) {
        long long s = in_sizes[i];
        void* p = d_in[i];
        switch (s) {
            case 8192:      idx = (const int*)p; break;
            case 131072:    cfi = (const int*)p; break;
            case 1600000:   root_cat  = (const int*)p; break;
            case 8000000:   child_cat = (const int*)p; break;
            case 12800000:  root_num  = (const float*)p; break;
            case 64000000:  child_num = (const float*)p; break;
            case 25600000:  emb_root  = (const float*)p; break;
            case 51200000:  emb_child = (const float*)p; break;
            case 36864:     W = (const float*)p; break;
            case 32:        bias = (const float*)p; break;
            case 64:
                if (!gamma_r) gamma_r = (const float*)p; else beta_r = (const float*)p;
                break;
            case 128:
                if (!gamma_c) gamma_c = (const float*)p; else beta_c = (const float*)p;
                break;
            default: break;
        }
    }

    float* out = (float*)d_out;

    const int big1_smem = DIM * OUTD * (int)sizeof(float);   // 8192 B (>= stats rid)
    const int big2_smem = NC * OUTD * (int)sizeof(float);    // 16384 B

    k_reset<<<1, 256>>>();
    k_big1<<<BIG1_BLKS, 256, big1_smem>>>(cfi, child_num, idx, root_num, emb_child, W);
    k_finalize<<<1, 1024>>>(gamma_c, beta_c, gamma_r, beta_r, W, bias);
    k_big2<<<BIG2_BLKS, 256, big2_smem>>>(cfi, child_cat, child_num,
                                          idx, root_cat, root_num, emb_root, out);
}